// round 13
// baseline (speedup 1.0000x reference)
#include <cuda_runtime.h>
#include <cuda_fp16.h>
#include <math.h>
#include <stdint.h>

#define B_ 4
#define S_ 2048
#define D_ 512
#define H_ 8
#define DH_ 64
#define M_ (B_ * S_)   // 8192

// ---------------- scratch (device globals; no allocation allowed) ----------------
__device__ __half g_x0h[(size_t)M_ * D_], g_x0l[(size_t)M_ * D_];
__device__ __half g_x1h[(size_t)M_ * D_], g_x1l[(size_t)M_ * D_];
__device__ __half g_x2h[(size_t)M_ * D_], g_x2l[(size_t)M_ * D_];
__device__ __half g_q1[(size_t)M_ * D_];
__device__ __half g_k1[(size_t)M_ * D_];
__device__ __half g_v1[(size_t)M_ * D_];
__device__ __half g_oh[(size_t)M_ * D_], g_ol[(size_t)M_ * D_];
__device__ __half g_w0[(size_t)D_ * D_];
__device__ __half g_w1[(size_t)D_ * D_];
__device__ __half g_w2[(size_t)D_ * D_];
__device__ __half g_w3[(size_t)D_ * D_];

// ================= helpers =================
__device__ __forceinline__ uint32_t smem_u32(const void* p) {
    uint32_t a;
    asm("{ .reg .u64 t; cvta.to.shared.u64 t, %1; cvt.u32.u64 %0, t; }" : "=r"(a) : "l"(p));
    return a;
}
__device__ __forceinline__ void split2h(float a, float b, uint32_t& hi, uint32_t& lo) {
    __half ha = __float2half_rn(a);
    __half hb = __float2half_rn(b);
    __half2 hv = __halves2half2(ha, hb);
    __half2 lv = __floats2half2_rn(a - __half2float(ha), b - __half2float(hb));
    hi = *reinterpret_cast<uint32_t*>(&hv);
    lo = *reinterpret_cast<uint32_t*>(&lv);
}
__device__ __forceinline__ uint32_t pack2h(float a, float b) {
    __half2 v = __floats2half2_rn(a, b);
    return *reinterpret_cast<uint32_t*>(&v);
}
__device__ __forceinline__ float ex2f(float x) {
    float r;
    asm("ex2.approx.f32 %0, %1;" : "=f"(r) : "f"(x));
    return r;
}
__device__ __forceinline__ void mma_f16(float* c, const uint32_t* a,
                                        uint32_t b0, uint32_t b1) {
    asm volatile(
        "mma.sync.aligned.m16n8k16.row.col.f32.f16.f16.f32 "
        "{%0,%1,%2,%3}, {%4,%5,%6,%7}, {%8,%9}, {%0,%1,%2,%3};"
        : "+f"(c[0]), "+f"(c[1]), "+f"(c[2]), "+f"(c[3])
        : "r"(a[0]), "r"(a[1]), "r"(a[2]), "r"(a[3]), "r"(b0), "r"(b1));
}
__device__ __forceinline__ void ldmx4(uint32_t* r, uint32_t addr) {
    asm volatile("ldmatrix.sync.aligned.m8n8.x4.shared.b16 {%0,%1,%2,%3}, [%4];"
                 : "=r"(r[0]), "=r"(r[1]), "=r"(r[2]), "=r"(r[3]) : "r"(addr));
}
__device__ __forceinline__ void ldmx4t(uint32_t* r, uint32_t addr) {
    asm volatile("ldmatrix.sync.aligned.m8n8.x4.trans.shared.b16 {%0,%1,%2,%3}, [%4];"
                 : "=r"(r[0]), "=r"(r[1]), "=r"(r[2]), "=r"(r[3]) : "r"(addr));
}
#define CP16(dst, src) \
    asm volatile("cp.async.cg.shared.global [%0], [%1], 16;" :: "r"(dst), "l"(src) : "memory")
#define CP_COMMIT() asm volatile("cp.async.commit_group;" ::: "memory")
#define CP_WAIT(n)  asm volatile("cp.async.wait_group %0;" :: "n"(n) : "memory")

// ---------------- prep kernels ----------------
__global__ void split_act3_kernel(const float* __restrict__ X0, const float* __restrict__ X1,
                                  const float* __restrict__ X2,
                                  __half* __restrict__ h0, __half* __restrict__ l0,
                                  __half* __restrict__ h1, __half* __restrict__ l1,
                                  __half* __restrict__ h2, __half* __restrict__ l2)
{
    const int which = blockIdx.y;
    const float* X = (which == 0) ? X0 : (which == 1) ? X1 : X2;
    __half* hh = (which == 0) ? h0 : (which == 1) ? h1 : h2;
    __half* ll = (which == 0) ? l0 : (which == 1) ? l1 : l2;
    size_t i = (size_t)blockIdx.x * blockDim.x + threadIdx.x;
    float4 v = __ldg((const float4*)X + i);
    uint32_t ha, la, hb, lb;
    split2h(v.x, v.y, ha, la);
    split2h(v.z, v.w, hb, lb);
    ((uint2*)hh)[i] = make_uint2(ha, hb);
    ((uint2*)ll)[i] = make_uint2(la, lb);
}

__global__ void split_w4_kernel(const float* __restrict__ W0, const float* __restrict__ W1,
                                const float* __restrict__ W2, const float* __restrict__ W3,
                                __half* __restrict__ t0, __half* __restrict__ t1,
                                __half* __restrict__ t2, __half* __restrict__ t3)
{
    const int which = blockIdx.y;
    const float* W = (which == 0) ? W0 : (which == 1) ? W1 : (which == 2) ? W2 : W3;
    __half* th = (which == 0) ? t0 : (which == 1) ? t1 : (which == 2) ? t2 : t3;
    int idx = blockIdx.x * blockDim.x + threadIdx.x;  // n*512 + k
    int n = idx >> 9, k = idx & 511;
    th[idx] = __float2half_rn(__ldg(W + (size_t)k * D_ + n));
}

// ---------------- cp.async double-buffered fp16 2-term GEMM ----------------
#define GAH 0
#define GAL 16384
#define GW  32768
#define GBUF 49152
#define GSMEM (2 * GBUF)   // 96 KB

// OUT: 0 = fp32, 1 = split fp16 hi/lo, 2 = single rounded fp16
template <int OUT>
__device__ __forceinline__ void gemm_body(
    const __half* __restrict__ Ah, const __half* __restrict__ Al,
    const __half* __restrict__ Wt,
    float* __restrict__ Cf, __half* __restrict__ Ch, __half* __restrict__ Cl,
    float alpha, char* smem, int m0, int n0)
{
    const uint32_t sb = smem_u32(smem);
    const int tid = threadIdx.x;
    const int w = tid >> 5;
    const int lane = tid & 31;
    const int group = lane >> 2, tig = lane & 3;
    const int m_ = lane >> 3, r_ = lane & 7;
    const int rsel = m_ >> 1, kodd = m_ & 1;
    const int wr = w >> 1;
    const int wc = w & 1;

    float cacc[2][8][4];
#pragma unroll
    for (int mt = 0; mt < 2; ++mt)
#pragma unroll
        for (int nt = 0; nt < 8; ++nt)
#pragma unroll
            for (int j = 0; j < 4; ++j) cacc[mt][nt][j] = 0.f;

    const int tok = tid >> 1, half_ = tid & 1;
    const uint32_t arow0 = (uint32_t)((wr * 32 + kodd * 8 + r_) * 128);
    const uint32_t arow1 = arow0 + 16 * 128;
    const uint32_t brow = (uint32_t)((wc * 64 + rsel * 8 + r_) * 128);

    auto issue = [&](int s, int buf) {
        const uint32_t bb = sb + buf * GBUF;
        const size_t abase = (size_t)(m0 + tok) * D_ + s * 64 + half_ * 32;
#pragma unroll
        for (int i = 0; i < 4; ++i) {
            const int chunk = half_ * 4 + i;
            const uint32_t off = (uint32_t)(tok * 128 + ((chunk ^ (tok & 7)) << 4));
            CP16(bb + GAH + off, Ah + abase + i * 8);
            CP16(bb + GAL + off, Al + abase + i * 8);
        }
        const size_t wbase = (size_t)(n0 + tok) * D_ + s * 64 + half_ * 32;
#pragma unroll
        for (int i = 0; i < 4; ++i) {
            const int chunk = half_ * 4 + i;
            const uint32_t off = (uint32_t)(tok * 128 + ((chunk ^ (tok & 7)) << 4));
            CP16(bb + GW + off, Wt + wbase + i * 8);
        }
        CP_COMMIT();
    };

    issue(0, 0);

    for (int s = 0; s < D_ / 64; ++s) {
        if (s + 1 < D_ / 64) { issue(s + 1, (s + 1) & 1); CP_WAIT(1); }
        else                 { CP_WAIT(0); }
        __syncthreads();

        const uint32_t bb = sb + (s & 1) * GBUF;

#pragma unroll
        for (int ks = 0; ks < 4; ++ks) {
            const uint32_t aoff = (uint32_t)(((2 * ks + rsel) ^ r_) << 4);
            uint32_t ah0[4], ah1[4], al0[4], al1[4];
            ldmx4(ah0, bb + GAH + arow0 + aoff);
            ldmx4(ah1, bb + GAH + arow1 + aoff);
            ldmx4(al0, bb + GAL + arow0 + aoff);
            ldmx4(al1, bb + GAL + arow1 + aoff);
            const uint32_t csw = (uint32_t)(((2 * ks + kodd) ^ r_) << 4);
#pragma unroll
            for (int ntp = 0; ntp < 4; ++ntp) {
                uint32_t bh[4];
                ldmx4(bh, bb + GW + brow + (uint32_t)(ntp * 2048) + csw);
                mma_f16(cacc[0][2*ntp],     ah0, bh[0], bh[1]);
                mma_f16(cacc[0][2*ntp + 1], ah0, bh[2], bh[3]);
                mma_f16(cacc[1][2*ntp],     ah1, bh[0], bh[1]);
                mma_f16(cacc[1][2*ntp + 1], ah1, bh[2], bh[3]);
                mma_f16(cacc[0][2*ntp],     al0, bh[0], bh[1]);
                mma_f16(cacc[0][2*ntp + 1], al0, bh[2], bh[3]);
                mma_f16(cacc[1][2*ntp],     al1, bh[0], bh[1]);
                mma_f16(cacc[1][2*ntp + 1], al1, bh[2], bh[3]);
            }
        }
        __syncthreads();
    }

#pragma unroll
    for (int mt = 0; mt < 2; ++mt) {
        const size_t row = (size_t)(m0 + wr * 32 + mt * 16 + group);
#pragma unroll
        for (int nt = 0; nt < 8; ++nt) {
            const int col = n0 + wc * 64 + nt * 8 + 2 * tig;
            const float v0 = cacc[mt][nt][0] * alpha, v1 = cacc[mt][nt][1] * alpha;
            const float v2 = cacc[mt][nt][2] * alpha, v3 = cacc[mt][nt][3] * alpha;
            if (OUT == 1) {
                uint32_t h0, l0, h1, l1;
                split2h(v0, v1, h0, l0);
                split2h(v2, v3, h1, l1);
                *(uint32_t*)(Ch + row * D_ + col) = h0;
                *(uint32_t*)(Cl + row * D_ + col) = l0;
                *(uint32_t*)(Ch + (row + 8) * D_ + col) = h1;
                *(uint32_t*)(Cl + (row + 8) * D_ + col) = l1;
            } else if (OUT == 2) {
                *(__half2*)(Ch + row * D_ + col) = __floats2half2_rn(v0, v1);
                *(__half2*)(Ch + (row + 8) * D_ + col) = __floats2half2_rn(v2, v3);
            } else {
                *(float2*)(Cf + row * D_ + col) = make_float2(v0, v1);
                *(float2*)(Cf + (row + 8) * D_ + col) = make_float2(v2, v3);
            }
        }
    }
}

__global__ __launch_bounds__(256, 2)
void gemm_qkv_kernel(const __half* __restrict__ x0h, const __half* __restrict__ x0l,
                     const __half* __restrict__ x1h, const __half* __restrict__ x1l,
                     const __half* __restrict__ x2h, const __half* __restrict__ x2l,
                     const __half* __restrict__ w0, const __half* __restrict__ w1,
                     const __half* __restrict__ w2,
                     __half* __restrict__ q1, __half* __restrict__ k1,
                     __half* __restrict__ v1)
{
    extern __shared__ char smem[];
    const int z = blockIdx.z;
    const int m0 = blockIdx.y * 128, n0 = blockIdx.x * 128;
    const float qalpha = 0.125f * 1.4426950408889634f;
    if (z == 0)
        gemm_body<2>(x0h, x0l, w0, nullptr, q1, nullptr, qalpha, smem, m0, n0);
    else if (z == 1)
        gemm_body<2>(x1h, x1l, w1, nullptr, k1, nullptr, 1.0f, smem, m0, n0);
    else
        gemm_body<2>(x2h, x2l, w2, nullptr, v1, nullptr, 1.0f, smem, m0, n0);
}

__global__ __launch_bounds__(256, 2)
void gemm_out_kernel(const __half* __restrict__ Ah, const __half* __restrict__ Al,
                     const __half* __restrict__ Wt, float* __restrict__ Cf)
{
    extern __shared__ char smem[];
    gemm_body<0>(Ah, Al, Wt, Cf, nullptr, nullptr, 1.0f, smem,
                 blockIdx.y * 128, blockIdx.x * 128);
}

// ================= flash attention: 256 q rows/CTA, 32 q rows/warp =================
#define BK 0
#define BV 8192
#define BUF_SZ 16384
#define ATT_SMEM 32768
#define NTILES (S_ / 64)   // 32

__global__ __launch_bounds__(256, 2)
void attn_mma_kernel(const __half* __restrict__ Q1,
                     const __half* __restrict__ K1, const __half* __restrict__ V1,
                     __half* __restrict__ Oh, __half* __restrict__ Ol)
{
    extern __shared__ char smem[];
    const uint32_t sb = smem_u32(smem);
    const int tid = threadIdx.x;
    const int w = tid >> 5;
    const int lane = tid & 31;
    const int group = lane >> 2, tig = lane & 3;
    const int m_ = lane >> 3, r_ = lane & 7;
    const int rsel = m_ >> 1, kodd = m_ & 1;
    const int bh_ = blockIdx.y;
    const int b = bh_ >> 3, h = bh_ & 7;
    const int q0 = blockIdx.x * 256;          // 256 q rows per CTA

    const uint32_t krow = (uint32_t)((rsel * 8 + r_) * 128);
    const int stok = tid >> 2;
    const int sc0 = (tid & 3) * 2;
    const size_t kvbase = (size_t)(b * S_) * D_ + h * DH_;

    // ---- Q fragments: two m-tiles per warp (rows w*32 .. w*32+31) ----
    uint32_t qh[2][4][4];
#pragma unroll
    for (int mt = 0; mt < 2; ++mt) {
        const size_t qrow = (size_t)(b * S_ + q0 + w * 32 + mt * 16 + group);
        const __half* qhp = Q1 + qrow * D_ + h * DH_;
#pragma unroll
        for (int ks = 0; ks < 4; ++ks) {
            const int c = ks * 16 + 2 * tig;
            qh[mt][ks][0] = *(const uint32_t*)(qhp + c);
            qh[mt][ks][1] = *(const uint32_t*)(qhp + 8 * D_ + c);
            qh[mt][ks][2] = *(const uint32_t*)(qhp + c + 8);
            qh[mt][ks][3] = *(const uint32_t*)(qhp + 8 * D_ + c + 8);
        }
    }

    float oacc[2][8][4];
#pragma unroll
    for (int mt = 0; mt < 2; ++mt)
#pragma unroll
        for (int i = 0; i < 8; ++i)
#pragma unroll
            for (int j = 0; j < 4; ++j) oacc[mt][i][j] = 0.f;
    float lsum[2][2] = {{0.f, 0.f}, {0.f, 0.f}};

    auto issue_tile = [&](int t, int buf) {
        const size_t g = kvbase + (size_t)(t * 64 + stok) * D_;
        const uint32_t bufb = sb + buf * BUF_SZ;
#pragma unroll
        for (int i = 0; i < 2; ++i) {
            const int c = sc0 + i;
            const uint32_t off = (uint32_t)(stok * 128 + ((c ^ (stok & 7)) << 4));
            const size_t ge = g + c * 8;
            CP16(bufb + BK + off, K1 + ge);
            CP16(bufb + BV + off, V1 + ge);
        }
        CP_COMMIT();
    };

    issue_tile(0, 0);

    for (int t = 0; t < NTILES; ++t) {
        if (t + 1 < NTILES) { issue_tile(t + 1, (t + 1) & 1); CP_WAIT(1); }
        else                { CP_WAIT(0); }
        __syncthreads();

        const uint32_t bufb = sb + (t & 1) * BUF_SZ;

#pragma unroll
        for (int ks2 = 0; ks2 < 4; ++ks2) {
            // ---- QK for both m-tiles (B-frag loaded once, 4 MMAs) ----
            float sacc[2][2][4];
#pragma unroll
            for (int mt = 0; mt < 2; ++mt)
#pragma unroll
                for (int j = 0; j < 4; ++j) { sacc[mt][0][j] = 0.f; sacc[mt][1][j] = 0.f; }
            const uint32_t ntbase = (uint32_t)(ks2 * 2048);
#pragma unroll
            for (int ks = 0; ks < 4; ++ks) {
                const uint32_t csw = (uint32_t)(((2 * ks + kodd) ^ r_) << 4);
                uint32_t bhv[4];
                ldmx4(bhv, bufb + BK + krow + ntbase + csw);
                mma_f16(sacc[0][0], qh[0][ks], bhv[0], bhv[1]);
                mma_f16(sacc[0][1], qh[0][ks], bhv[2], bhv[3]);
                mma_f16(sacc[1][0], qh[1][ks], bhv[0], bhv[1]);
                mma_f16(sacc[1][1], qh[1][ks], bhv[2], bhv[3]);
            }
            // ---- softmax both m-tiles ----
            uint32_t pha[2][4];
#pragma unroll
            for (int mt = 0; mt < 2; ++mt) {
                const float p00 = ex2f(sacc[mt][0][0]), p01 = ex2f(sacc[mt][0][1]);
                const float p02 = ex2f(sacc[mt][0][2]), p03 = ex2f(sacc[mt][0][3]);
                const float p10 = ex2f(sacc[mt][1][0]), p11 = ex2f(sacc[mt][1][1]);
                const float p12 = ex2f(sacc[mt][1][2]), p13 = ex2f(sacc[mt][1][3]);
                lsum[mt][0] += p00 + p01 + p10 + p11;
                lsum[mt][1] += p02 + p03 + p12 + p13;
                pha[mt][0] = pack2h(p00, p01);
                pha[mt][1] = pack2h(p02, p03);
                pha[mt][2] = pack2h(p10, p11);
                pha[mt][3] = pack2h(p12, p13);
            }

            // ---- PV for both m-tiles (B-frag loaded once, 4 MMAs) ----
            const uint32_t vrow = (uint32_t)((ks2 * 16 + kodd * 8 + r_) * 128);
#pragma unroll
            for (int ntp = 0; ntp < 4; ++ntp) {
                const uint32_t csw = (uint32_t)(((2 * ntp + rsel) ^ r_) << 4);
                uint32_t bhv[4];
                ldmx4t(bhv, bufb + BV + vrow + csw);
                mma_f16(oacc[0][2*ntp],     pha[0], bhv[0], bhv[1]);
                mma_f16(oacc[0][2*ntp + 1], pha[0], bhv[2], bhv[3]);
                mma_f16(oacc[1][2*ntp],     pha[1], bhv[0], bhv[1]);
                mma_f16(oacc[1][2*ntp + 1], pha[1], bhv[2], bhv[3]);
            }
        }
        __syncthreads();
    }

#pragma unroll
    for (int mt = 0; mt < 2; ++mt) {
        float l0 = lsum[mt][0], l1 = lsum[mt][1];
        l0 += __shfl_xor_sync(0xffffffffu, l0, 1);
        l0 += __shfl_xor_sync(0xffffffffu, l0, 2);
        l1 += __shfl_xor_sync(0xffffffffu, l1, 1);
        l1 += __shfl_xor_sync(0xffffffffu, l1, 2);
        const float inv0 = 1.f / l0;
        const float inv1 = 1.f / l1;

        const size_t orow = (size_t)(b * S_ + q0 + w * 32 + mt * 16 + group);
#pragma unroll
        for (int nt = 0; nt < 8; ++nt) {
            const int col = h * DH_ + nt * 8 + 2 * tig;
            uint32_t h0, l0b, h1, l1b;
            split2h(oacc[mt][nt][0] * inv0, oacc[mt][nt][1] * inv0, h0, l0b);
            split2h(oacc[mt][nt][2] * inv1, oacc[mt][nt][3] * inv1, h1, l1b);
            *(uint32_t*)(Oh + orow * D_ + col) = h0;
            *(uint32_t*)(Ol + orow * D_ + col) = l0b;
            *(uint32_t*)(Oh + (orow + 8) * D_ + col) = h1;
            *(uint32_t*)(Ol + (orow + 8) * D_ + col) = l1b;
        }
    }
}

// ---------------- launch ----------------
extern "C" void kernel_launch(void* const* d_in, const int* in_sizes, int n_in,
                              void* d_out, int out_size)
{
    const float* xq = (const float*)d_in[0];
    const float* xk = (const float*)d_in[1];
    const float* xv = (const float*)d_in[2];
    const float* Wq = (const float*)d_in[3];
    const float* Wk = (const float*)d_in[4];
    const float* Wv = (const float*)d_in[5];
    const float* Wo = (const float*)d_in[6];
    float* out = (float*)d_out;

    void *x0h, *x0l, *x1h, *x1l, *x2h, *x2l;
    void *q1, *k1, *v1, *oh, *ol;
    void *w0, *w1, *w2, *w3;
    cudaGetSymbolAddress(&x0h, g_x0h); cudaGetSymbolAddress(&x0l, g_x0l);
    cudaGetSymbolAddress(&x1h, g_x1h); cudaGetSymbolAddress(&x1l, g_x1l);
    cudaGetSymbolAddress(&x2h, g_x2h); cudaGetSymbolAddress(&x2l, g_x2l);
    cudaGetSymbolAddress(&q1, g_q1);
    cudaGetSymbolAddress(&k1, g_k1);   cudaGetSymbolAddress(&v1, g_v1);
    cudaGetSymbolAddress(&oh, g_oh);   cudaGetSymbolAddress(&ol, g_ol);
    cudaGetSymbolAddress(&w0, g_w0);   cudaGetSymbolAddress(&w1, g_w1);
    cudaGetSymbolAddress(&w2, g_w2);   cudaGetSymbolAddress(&w3, g_w3);

    static int init_done = 0;
    if (!init_done) {
        cudaFuncSetAttribute(attn_mma_kernel, cudaFuncAttributeMaxDynamicSharedMemorySize, ATT_SMEM);
        cudaFuncSetAttribute(gemm_qkv_kernel, cudaFuncAttributeMaxDynamicSharedMemorySize, GSMEM);
        cudaFuncSetAttribute(gemm_out_kernel, cudaFuncAttributeMaxDynamicSharedMemorySize, GSMEM);
        init_done = 1;
    }

    typedef __half hf;

    // prep
    dim3 agrid_s((M_ * D_ / 4) / 256, 3);
    split_act3_kernel<<<agrid_s, 256>>>(xq, xk, xv,
                                        (hf*)x0h, (hf*)x0l, (hf*)x1h, (hf*)x1l,
                                        (hf*)x2h, (hf*)x2l);
    dim3 wgrid((D_ * D_) / 256, 4);
    split_w4_kernel<<<wgrid, 256>>>(Wq, Wk, Wv, Wo,
                                    (hf*)w0, (hf*)w1, (hf*)w2, (hf*)w3);

    // merged Q/K/V projections
    dim3 qkvgrid(D_ / 128, M_ / 128, 3);   // (4, 64, 3)
    gemm_qkv_kernel<<<qkvgrid, 256, GSMEM>>>(
        (hf*)x0h, (hf*)x0l, (hf*)x1h, (hf*)x1l, (hf*)x2h, (hf*)x2l,
        (hf*)w0, (hf*)w1, (hf*)w2,
        (hf*)q1, (hf*)k1, (hf*)v1);

    // attention: 256 q rows per CTA -> 256 CTAs = single wave at 2 CTA/SM
    dim3 agrid(S_ / 256, B_ * H_);   // (8, 32)
    attn_mma_kernel<<<agrid, 256, ATT_SMEM>>>((hf*)q1, (hf*)k1, (hf*)v1,
                                              (hf*)oh, (hf*)ol);

    // output projection (fp32 out)
    dim3 ogrid(D_ / 128, M_ / 128);   // (4, 64)
    gemm_out_kernel<<<ogrid, 256, GSMEM>>>((hf*)oh, (hf*)ol, (hf*)w3, out);
}

// round 14
// speedup vs baseline: 1.0752x; 1.0752x over previous
#include <cuda_runtime.h>
#include <cuda_fp16.h>
#include <math.h>
#include <stdint.h>

#define B_ 4
#define S_ 2048
#define D_ 512
#define H_ 8
#define DH_ 64
#define M_ (B_ * S_)   // 8192

// ---------------- scratch (device globals; no allocation allowed) ----------------
__device__ __half g_x0h[(size_t)M_ * D_], g_x0l[(size_t)M_ * D_];
__device__ __half g_x1h[(size_t)M_ * D_], g_x1l[(size_t)M_ * D_];
__device__ __half g_x2h[(size_t)M_ * D_], g_x2l[(size_t)M_ * D_];
__device__ __half g_q1[(size_t)M_ * D_];
__device__ __half g_k1[(size_t)M_ * D_];
__device__ __half g_v1[(size_t)M_ * D_];
__device__ __half g_o1[(size_t)M_ * D_];   // single fp16 O
__device__ __half g_w0[(size_t)D_ * D_];
__device__ __half g_w1[(size_t)D_ * D_];
__device__ __half g_w2[(size_t)D_ * D_];
__device__ __half g_w3[(size_t)D_ * D_];

// ================= helpers =================
__device__ __forceinline__ uint32_t smem_u32(const void* p) {
    uint32_t a;
    asm("{ .reg .u64 t; cvta.to.shared.u64 t, %1; cvt.u32.u64 %0, t; }" : "=r"(a) : "l"(p));
    return a;
}
__device__ __forceinline__ void split2h(float a, float b, uint32_t& hi, uint32_t& lo) {
    __half ha = __float2half_rn(a);
    __half hb = __float2half_rn(b);
    __half2 hv = __halves2half2(ha, hb);
    __half2 lv = __floats2half2_rn(a - __half2float(ha), b - __half2float(hb));
    hi = *reinterpret_cast<uint32_t*>(&hv);
    lo = *reinterpret_cast<uint32_t*>(&lv);
}
__device__ __forceinline__ uint32_t pack2h(float a, float b) {
    __half2 v = __floats2half2_rn(a, b);
    return *reinterpret_cast<uint32_t*>(&v);
}
__device__ __forceinline__ float ex2f(float x) {
    float r;
    asm("ex2.approx.f32 %0, %1;" : "=f"(r) : "f"(x));
    return r;
}
__device__ __forceinline__ void mma_f16(float* c, const uint32_t* a,
                                        uint32_t b0, uint32_t b1) {
    asm volatile(
        "mma.sync.aligned.m16n8k16.row.col.f32.f16.f16.f32 "
        "{%0,%1,%2,%3}, {%4,%5,%6,%7}, {%8,%9}, {%0,%1,%2,%3};"
        : "+f"(c[0]), "+f"(c[1]), "+f"(c[2]), "+f"(c[3])
        : "r"(a[0]), "r"(a[1]), "r"(a[2]), "r"(a[3]), "r"(b0), "r"(b1));
}
__device__ __forceinline__ void ldmx4(uint32_t* r, uint32_t addr) {
    asm volatile("ldmatrix.sync.aligned.m8n8.x4.shared.b16 {%0,%1,%2,%3}, [%4];"
                 : "=r"(r[0]), "=r"(r[1]), "=r"(r[2]), "=r"(r[3]) : "r"(addr));
}
__device__ __forceinline__ void ldmx4t(uint32_t* r, uint32_t addr) {
    asm volatile("ldmatrix.sync.aligned.m8n8.x4.trans.shared.b16 {%0,%1,%2,%3}, [%4];"
                 : "=r"(r[0]), "=r"(r[1]), "=r"(r[2]), "=r"(r[3]) : "r"(addr));
}
#define CP16(dst, src) \
    asm volatile("cp.async.cg.shared.global [%0], [%1], 16;" :: "r"(dst), "l"(src) : "memory")
#define CP_COMMIT() asm volatile("cp.async.commit_group;" ::: "memory")
#define CP_WAIT(n)  asm volatile("cp.async.wait_group %0;" :: "n"(n) : "memory")

// ---------------- prep kernels ----------------
__global__ void split_act3_kernel(const float* __restrict__ X0, const float* __restrict__ X1,
                                  const float* __restrict__ X2,
                                  __half* __restrict__ h0, __half* __restrict__ l0,
                                  __half* __restrict__ h1, __half* __restrict__ l1,
                                  __half* __restrict__ h2, __half* __restrict__ l2)
{
    const int which = blockIdx.y;
    const float* X = (which == 0) ? X0 : (which == 1) ? X1 : X2;
    __half* hh = (which == 0) ? h0 : (which == 1) ? h1 : h2;
    __half* ll = (which == 0) ? l0 : (which == 1) ? l1 : l2;
    size_t i = (size_t)blockIdx.x * blockDim.x + threadIdx.x;
    float4 v = __ldg((const float4*)X + i);
    uint32_t ha, la, hb, lb;
    split2h(v.x, v.y, ha, la);
    split2h(v.z, v.w, hb, lb);
    ((uint2*)hh)[i] = make_uint2(ha, hb);
    ((uint2*)ll)[i] = make_uint2(la, lb);
}

__global__ void split_w4_kernel(const float* __restrict__ W0, const float* __restrict__ W1,
                                const float* __restrict__ W2, const float* __restrict__ W3,
                                __half* __restrict__ t0, __half* __restrict__ t1,
                                __half* __restrict__ t2, __half* __restrict__ t3)
{
    const int which = blockIdx.y;
    const float* W = (which == 0) ? W0 : (which == 1) ? W1 : (which == 2) ? W2 : W3;
    __half* th = (which == 0) ? t0 : (which == 1) ? t1 : (which == 2) ? t2 : t3;
    int idx = blockIdx.x * blockDim.x + threadIdx.x;  // n*512 + k
    int n = idx >> 9, k = idx & 511;
    th[idx] = __float2half_rn(__ldg(W + (size_t)k * D_ + n));
}

// ---------------- cp.async double-buffered fp16 GEMM ----------------
// Tile: M=128, N=128, k-stage 64. 256 threads (8 warps, 4 m-blocks x 2 n-blocks).
#define GAH 0
#define GAL 16384
#define GW  32768
#define GBUF 49152
#define GSMEM (2 * GBUF)   // 96 KB

// OUT: 0 = fp32, 2 = single rounded fp16.  TWO_TERM: A split or single.
template <int OUT, bool TWO_TERM>
__device__ __forceinline__ void gemm_body(
    const __half* __restrict__ Ah, const __half* __restrict__ Al,
    const __half* __restrict__ Wt,
    float* __restrict__ Cf, __half* __restrict__ Ch,
    float alpha, char* smem, int m0, int n0)
{
    const uint32_t sb = smem_u32(smem);
    const int tid = threadIdx.x;
    const int w = tid >> 5;
    const int lane = tid & 31;
    const int group = lane >> 2, tig = lane & 3;
    const int m_ = lane >> 3, r_ = lane & 7;
    const int rsel = m_ >> 1, kodd = m_ & 1;
    const int wr = w >> 1;
    const int wc = w & 1;

    float cacc[2][8][4];
#pragma unroll
    for (int mt = 0; mt < 2; ++mt)
#pragma unroll
        for (int nt = 0; nt < 8; ++nt)
#pragma unroll
            for (int j = 0; j < 4; ++j) cacc[mt][nt][j] = 0.f;

    const int tok = tid >> 1, half_ = tid & 1;
    const uint32_t arow0 = (uint32_t)((wr * 32 + kodd * 8 + r_) * 128);
    const uint32_t arow1 = arow0 + 16 * 128;
    const uint32_t brow = (uint32_t)((wc * 64 + rsel * 8 + r_) * 128);

    auto issue = [&](int s, int buf) {
        const uint32_t bb = sb + buf * GBUF;
        const size_t abase = (size_t)(m0 + tok) * D_ + s * 64 + half_ * 32;
#pragma unroll
        for (int i = 0; i < 4; ++i) {
            const int chunk = half_ * 4 + i;
            const uint32_t off = (uint32_t)(tok * 128 + ((chunk ^ (tok & 7)) << 4));
            CP16(bb + GAH + off, Ah + abase + i * 8);
            if (TWO_TERM) CP16(bb + GAL + off, Al + abase + i * 8);
        }
        const size_t wbase = (size_t)(n0 + tok) * D_ + s * 64 + half_ * 32;
#pragma unroll
        for (int i = 0; i < 4; ++i) {
            const int chunk = half_ * 4 + i;
            const uint32_t off = (uint32_t)(tok * 128 + ((chunk ^ (tok & 7)) << 4));
            CP16(bb + GW + off, Wt + wbase + i * 8);
        }
        CP_COMMIT();
    };

    issue(0, 0);

    for (int s = 0; s < D_ / 64; ++s) {
        if (s + 1 < D_ / 64) { issue(s + 1, (s + 1) & 1); CP_WAIT(1); }
        else                 { CP_WAIT(0); }
        __syncthreads();

        const uint32_t bb = sb + (s & 1) * GBUF;

#pragma unroll
        for (int ks = 0; ks < 4; ++ks) {
            const uint32_t aoff = (uint32_t)(((2 * ks + rsel) ^ r_) << 4);
            uint32_t ah0[4], ah1[4], al0[4], al1[4];
            ldmx4(ah0, bb + GAH + arow0 + aoff);
            ldmx4(ah1, bb + GAH + arow1 + aoff);
            if (TWO_TERM) {
                ldmx4(al0, bb + GAL + arow0 + aoff);
                ldmx4(al1, bb + GAL + arow1 + aoff);
            }
            const uint32_t csw = (uint32_t)(((2 * ks + kodd) ^ r_) << 4);
#pragma unroll
            for (int ntp = 0; ntp < 4; ++ntp) {
                uint32_t bh[4];
                ldmx4(bh, bb + GW + brow + (uint32_t)(ntp * 2048) + csw);
                mma_f16(cacc[0][2*ntp],     ah0, bh[0], bh[1]);
                mma_f16(cacc[0][2*ntp + 1], ah0, bh[2], bh[3]);
                mma_f16(cacc[1][2*ntp],     ah1, bh[0], bh[1]);
                mma_f16(cacc[1][2*ntp + 1], ah1, bh[2], bh[3]);
                if (TWO_TERM) {
                    mma_f16(cacc[0][2*ntp],     al0, bh[0], bh[1]);
                    mma_f16(cacc[0][2*ntp + 1], al0, bh[2], bh[3]);
                    mma_f16(cacc[1][2*ntp],     al1, bh[0], bh[1]);
                    mma_f16(cacc[1][2*ntp + 1], al1, bh[2], bh[3]);
                }
            }
        }
        __syncthreads();
    }

#pragma unroll
    for (int mt = 0; mt < 2; ++mt) {
        const size_t row = (size_t)(m0 + wr * 32 + mt * 16 + group);
#pragma unroll
        for (int nt = 0; nt < 8; ++nt) {
            const int col = n0 + wc * 64 + nt * 8 + 2 * tig;
            const float v0 = cacc[mt][nt][0] * alpha, v1 = cacc[mt][nt][1] * alpha;
            const float v2 = cacc[mt][nt][2] * alpha, v3 = cacc[mt][nt][3] * alpha;
            if (OUT == 2) {
                *(__half2*)(Ch + row * D_ + col) = __floats2half2_rn(v0, v1);
                *(__half2*)(Ch + (row + 8) * D_ + col) = __floats2half2_rn(v2, v3);
            } else {
                *(float2*)(Cf + row * D_ + col) = make_float2(v0, v1);
                *(float2*)(Cf + (row + 8) * D_ + col) = make_float2(v2, v3);
            }
        }
    }
}

__global__ __launch_bounds__(256, 2)
void gemm_qkv_kernel(const __half* __restrict__ x0h, const __half* __restrict__ x0l,
                     const __half* __restrict__ x1h, const __half* __restrict__ x1l,
                     const __half* __restrict__ x2h, const __half* __restrict__ x2l,
                     const __half* __restrict__ w0, const __half* __restrict__ w1,
                     const __half* __restrict__ w2,
                     __half* __restrict__ q1, __half* __restrict__ k1,
                     __half* __restrict__ v1)
{
    extern __shared__ char smem[];
    const int z = blockIdx.z;
    const int m0 = blockIdx.y * 128, n0 = blockIdx.x * 128;
    const float qalpha = 0.125f * 1.4426950408889634f;
    if (z == 0)
        gemm_body<2, true>(x0h, x0l, w0, nullptr, q1, qalpha, smem, m0, n0);
    else if (z == 1)
        gemm_body<2, true>(x1h, x1l, w1, nullptr, k1, 1.0f, smem, m0, n0);
    else
        gemm_body<2, true>(x2h, x2l, w2, nullptr, v1, 1.0f, smem, m0, n0);
}

// out-projection: single-term A (O is single fp16)
__global__ __launch_bounds__(256, 2)
void gemm_out_kernel(const __half* __restrict__ A1,
                     const __half* __restrict__ Wt, float* __restrict__ Cf)
{
    extern __shared__ char smem[];
    gemm_body<0, false>(A1, nullptr, Wt, Cf, nullptr, 1.0f, smem,
                        blockIdx.y * 128, blockIdx.x * 128);
}

// ================= flash attention (R12 config: 128 q rows/CTA, 16/warp) =================
#define BK 0
#define BV 8192
#define BUF_SZ 16384
#define ATT_SMEM 32768
#define NTILES (S_ / 64)   // 32

__global__ __launch_bounds__(256, 2)
void attn_mma_kernel(const __half* __restrict__ Q1,
                     const __half* __restrict__ K1, const __half* __restrict__ V1,
                     __half* __restrict__ O1)
{
    extern __shared__ char smem[];
    const uint32_t sb = smem_u32(smem);
    const int tid = threadIdx.x;
    const int w = tid >> 5;
    const int lane = tid & 31;
    const int group = lane >> 2, tig = lane & 3;
    const int m_ = lane >> 3, r_ = lane & 7;
    const int rsel = m_ >> 1, kodd = m_ & 1;
    const int bh_ = blockIdx.y;
    const int b = bh_ >> 3, h = bh_ & 7;
    const int q0 = blockIdx.x * 128;

    const uint32_t krow = (uint32_t)((rsel * 8 + r_) * 128);
    const int stok = tid >> 2;
    const int sc0 = (tid & 3) * 2;
    const size_t kvbase = (size_t)(b * S_) * D_ + h * DH_;

    // ---- Q fragments (single fp16, pre-scaled by log2e/8) ----
    uint32_t qh[4][4];
    {
        const size_t qrow = (size_t)(b * S_ + q0 + w * 16 + group);
        const __half* qhp = Q1 + qrow * D_ + h * DH_;
#pragma unroll
        for (int ks = 0; ks < 4; ++ks) {
            const int c = ks * 16 + 2 * tig;
            qh[ks][0] = *(const uint32_t*)(qhp + c);
            qh[ks][1] = *(const uint32_t*)(qhp + 8 * D_ + c);
            qh[ks][2] = *(const uint32_t*)(qhp + c + 8);
            qh[ks][3] = *(const uint32_t*)(qhp + 8 * D_ + c + 8);
        }
    }

    float oacc[8][4];
#pragma unroll
    for (int i = 0; i < 8; ++i)
#pragma unroll
        for (int j = 0; j < 4; ++j) oacc[i][j] = 0.f;
    float lsum0 = 0.f, lsum1 = 0.f;

    auto issue_tile = [&](int t, int buf) {
        const size_t g = kvbase + (size_t)(t * 64 + stok) * D_;
        const uint32_t bufb = sb + buf * BUF_SZ;
#pragma unroll
        for (int i = 0; i < 2; ++i) {
            const int c = sc0 + i;
            const uint32_t off = (uint32_t)(stok * 128 + ((c ^ (stok & 7)) << 4));
            const size_t ge = g + c * 8;
            CP16(bufb + BK + off, K1 + ge);
            CP16(bufb + BV + off, V1 + ge);
        }
        CP_COMMIT();
    };

    issue_tile(0, 0);

    for (int t = 0; t < NTILES; ++t) {
        if (t + 1 < NTILES) { issue_tile(t + 1, (t + 1) & 1); CP_WAIT(1); }
        else                { CP_WAIT(0); }
        __syncthreads();

        const uint32_t bufb = sb + (t & 1) * BUF_SZ;

#pragma unroll
        for (int ks2 = 0; ks2 < 4; ++ks2) {
            float sacc[2][4];
#pragma unroll
            for (int j = 0; j < 4; ++j) { sacc[0][j] = 0.f; sacc[1][j] = 0.f; }
            const uint32_t ntbase = (uint32_t)(ks2 * 2048);
#pragma unroll
            for (int ks = 0; ks < 4; ++ks) {
                const uint32_t csw = (uint32_t)(((2 * ks + kodd) ^ r_) << 4);
                uint32_t bhv[4];
                ldmx4(bhv, bufb + BK + krow + ntbase + csw);
                mma_f16(sacc[0], qh[ks], bhv[0], bhv[1]);
                mma_f16(sacc[1], qh[ks], bhv[2], bhv[3]);
            }
            const float p00 = ex2f(sacc[0][0]), p01 = ex2f(sacc[0][1]);
            const float p02 = ex2f(sacc[0][2]), p03 = ex2f(sacc[0][3]);
            const float p10 = ex2f(sacc[1][0]), p11 = ex2f(sacc[1][1]);
            const float p12 = ex2f(sacc[1][2]), p13 = ex2f(sacc[1][3]);
            lsum0 += p00 + p01 + p10 + p11;
            lsum1 += p02 + p03 + p12 + p13;
            uint32_t pha[4];
            pha[0] = pack2h(p00, p01);
            pha[1] = pack2h(p02, p03);
            pha[2] = pack2h(p10, p11);
            pha[3] = pack2h(p12, p13);

            const uint32_t vrow = (uint32_t)((ks2 * 16 + kodd * 8 + r_) * 128);
#pragma unroll
            for (int ntp = 0; ntp < 4; ++ntp) {
                const uint32_t csw = (uint32_t)(((2 * ntp + rsel) ^ r_) << 4);
                uint32_t bhv[4];
                ldmx4t(bhv, bufb + BV + vrow + csw);
                mma_f16(oacc[2*ntp],     pha, bhv[0], bhv[1]);
                mma_f16(oacc[2*ntp + 1], pha, bhv[2], bhv[3]);
            }
        }
        __syncthreads();
    }

    lsum0 += __shfl_xor_sync(0xffffffffu, lsum0, 1);
    lsum0 += __shfl_xor_sync(0xffffffffu, lsum0, 2);
    lsum1 += __shfl_xor_sync(0xffffffffu, lsum1, 1);
    lsum1 += __shfl_xor_sync(0xffffffffu, lsum1, 2);
    const float inv0 = 1.f / lsum0;
    const float inv1 = 1.f / lsum1;

    const size_t orow = (size_t)(b * S_ + q0 + w * 16 + group);
#pragma unroll
    for (int nt = 0; nt < 8; ++nt) {
        const int col = h * DH_ + nt * 8 + 2 * tig;
        *(__half2*)(O1 + orow * D_ + col) =
            __floats2half2_rn(oacc[nt][0] * inv0, oacc[nt][1] * inv0);
        *(__half2*)(O1 + (orow + 8) * D_ + col) =
            __floats2half2_rn(oacc[nt][2] * inv1, oacc[nt][3] * inv1);
    }
}

// ---------------- launch ----------------
extern "C" void kernel_launch(void* const* d_in, const int* in_sizes, int n_in,
                              void* d_out, int out_size)
{
    const float* xq = (const float*)d_in[0];
    const float* xk = (const float*)d_in[1];
    const float* xv = (const float*)d_in[2];
    const float* Wq = (const float*)d_in[3];
    const float* Wk = (const float*)d_in[4];
    const float* Wv = (const float*)d_in[5];
    const float* Wo = (const float*)d_in[6];
    float* out = (float*)d_out;

    void *x0h, *x0l, *x1h, *x1l, *x2h, *x2l;
    void *q1, *k1, *v1, *o1;
    void *w0, *w1, *w2, *w3;
    cudaGetSymbolAddress(&x0h, g_x0h); cudaGetSymbolAddress(&x0l, g_x0l);
    cudaGetSymbolAddress(&x1h, g_x1h); cudaGetSymbolAddress(&x1l, g_x1l);
    cudaGetSymbolAddress(&x2h, g_x2h); cudaGetSymbolAddress(&x2l, g_x2l);
    cudaGetSymbolAddress(&q1, g_q1);
    cudaGetSymbolAddress(&k1, g_k1);   cudaGetSymbolAddress(&v1, g_v1);
    cudaGetSymbolAddress(&o1, g_o1);
    cudaGetSymbolAddress(&w0, g_w0);   cudaGetSymbolAddress(&w1, g_w1);
    cudaGetSymbolAddress(&w2, g_w2);   cudaGetSymbolAddress(&w3, g_w3);

    static int init_done = 0;
    if (!init_done) {
        cudaFuncSetAttribute(attn_mma_kernel, cudaFuncAttributeMaxDynamicSharedMemorySize, ATT_SMEM);
        cudaFuncSetAttribute(gemm_qkv_kernel, cudaFuncAttributeMaxDynamicSharedMemorySize, GSMEM);
        cudaFuncSetAttribute(gemm_out_kernel, cudaFuncAttributeMaxDynamicSharedMemorySize, GSMEM);
        init_done = 1;
    }

    typedef __half hf;

    // prep
    dim3 agrid_s((M_ * D_ / 4) / 256, 3);
    split_act3_kernel<<<agrid_s, 256>>>(xq, xk, xv,
                                        (hf*)x0h, (hf*)x0l, (hf*)x1h, (hf*)x1l,
                                        (hf*)x2h, (hf*)x2l);
    dim3 wgrid((D_ * D_) / 256, 4);
    split_w4_kernel<<<wgrid, 256>>>(Wq, Wk, Wv, Wo,
                                    (hf*)w0, (hf*)w1, (hf*)w2, (hf*)w3);

    // merged Q/K/V projections
    dim3 qkvgrid(D_ / 128, M_ / 128, 3);   // (4, 64, 3)
    gemm_qkv_kernel<<<qkvgrid, 256, GSMEM>>>(
        (hf*)x0h, (hf*)x0l, (hf*)x1h, (hf*)x1l, (hf*)x2h, (hf*)x2l,
        (hf*)w0, (hf*)w1, (hf*)w2,
        (hf*)q1, (hf*)k1, (hf*)v1);

    // attention (R12 config; single fp16 O out)
    dim3 agrid(S_ / 128, B_ * H_);   // (16, 32)
    attn_mma_kernel<<<agrid, 256, ATT_SMEM>>>((hf*)q1, (hf*)k1, (hf*)v1, (hf*)o1);

    // output projection (single-term A, fp32 out)
    dim3 ogrid(D_ / 128, M_ / 128);   // (4, 64)
    gemm_out_kernel<<<ogrid, 256, GSMEM>>>((hf*)o1, (hf*)w3, out);
}

// round 15
// speedup vs baseline: 1.1401x; 1.0604x over previous
#include <cuda_runtime.h>
#include <cuda_fp16.h>
#include <math.h>
#include <stdint.h>

#define B_ 4
#define S_ 2048
#define D_ 512
#define H_ 8
#define DH_ 64
#define M_ (B_ * S_)   // 8192

// ---------------- scratch (device globals; no allocation allowed) ----------------
__device__ __half g_x0[(size_t)M_ * D_];
__device__ __half g_x1[(size_t)M_ * D_];
__device__ __half g_x2[(size_t)M_ * D_];
__device__ __half g_q1[(size_t)M_ * D_];
__device__ __half g_k1[(size_t)M_ * D_];
__device__ __half g_v1[(size_t)M_ * D_];
__device__ __half g_o1[(size_t)M_ * D_];
__device__ __half g_w0[(size_t)D_ * D_];
__device__ __half g_w1[(size_t)D_ * D_];
__device__ __half g_w2[(size_t)D_ * D_];
__device__ __half g_w3[(size_t)D_ * D_];

// ================= helpers =================
__device__ __forceinline__ uint32_t smem_u32(const void* p) {
    uint32_t a;
    asm("{ .reg .u64 t; cvta.to.shared.u64 t, %1; cvt.u32.u64 %0, t; }" : "=r"(a) : "l"(p));
    return a;
}
__device__ __forceinline__ uint32_t pack2h(float a, float b) {
    __half2 v = __floats2half2_rn(a, b);
    return *reinterpret_cast<uint32_t*>(&v);
}
__device__ __forceinline__ float ex2f(float x) {
    float r;
    asm("ex2.approx.f32 %0, %1;" : "=f"(r) : "f"(x));
    return r;
}
__device__ __forceinline__ void mma_f16(float* c, const uint32_t* a,
                                        uint32_t b0, uint32_t b1) {
    asm volatile(
        "mma.sync.aligned.m16n8k16.row.col.f32.f16.f16.f32 "
        "{%0,%1,%2,%3}, {%4,%5,%6,%7}, {%8,%9}, {%0,%1,%2,%3};"
        : "+f"(c[0]), "+f"(c[1]), "+f"(c[2]), "+f"(c[3])
        : "r"(a[0]), "r"(a[1]), "r"(a[2]), "r"(a[3]), "r"(b0), "r"(b1));
}
__device__ __forceinline__ void ldmx4(uint32_t* r, uint32_t addr) {
    asm volatile("ldmatrix.sync.aligned.m8n8.x4.shared.b16 {%0,%1,%2,%3}, [%4];"
                 : "=r"(r[0]), "=r"(r[1]), "=r"(r[2]), "=r"(r[3]) : "r"(addr));
}
__device__ __forceinline__ void ldmx4t(uint32_t* r, uint32_t addr) {
    asm volatile("ldmatrix.sync.aligned.m8n8.x4.trans.shared.b16 {%0,%1,%2,%3}, [%4];"
                 : "=r"(r[0]), "=r"(r[1]), "=r"(r[2]), "=r"(r[3]) : "r"(addr));
}
#define CP16(dst, src) \
    asm volatile("cp.async.cg.shared.global [%0], [%1], 16;" :: "r"(dst), "l"(src) : "memory")
#define CP_COMMIT() asm volatile("cp.async.commit_group;" ::: "memory")
#define CP_WAIT(n)  asm volatile("cp.async.wait_group %0;" :: "n"(n) : "memory")

// ---------------- prep kernels ----------------
__global__ void round_act3_kernel(const float* __restrict__ X0, const float* __restrict__ X1,
                                  const float* __restrict__ X2,
                                  __half* __restrict__ y0, __half* __restrict__ y1,
                                  __half* __restrict__ y2)
{
    const int which = blockIdx.y;
    const float* X = (which == 0) ? X0 : (which == 1) ? X1 : X2;
    __half* Y = (which == 0) ? y0 : (which == 1) ? y1 : y2;
    size_t i = (size_t)blockIdx.x * blockDim.x + threadIdx.x;   // float4 index
    float4 v = __ldg((const float4*)X + i);
    uint32_t a = pack2h(v.x, v.y);
    uint32_t b = pack2h(v.z, v.w);
    ((uint2*)Y)[i] = make_uint2(a, b);
}

__global__ void split_w4_kernel(const float* __restrict__ W0, const float* __restrict__ W1,
                                const float* __restrict__ W2, const float* __restrict__ W3,
                                __half* __restrict__ t0, __half* __restrict__ t1,
                                __half* __restrict__ t2, __half* __restrict__ t3)
{
    const int which = blockIdx.y;
    const float* W = (which == 0) ? W0 : (which == 1) ? W1 : (which == 2) ? W2 : W3;
    __half* th = (which == 0) ? t0 : (which == 1) ? t1 : (which == 2) ? t2 : t3;
    int idx = blockIdx.x * blockDim.x + threadIdx.x;  // n*512 + k
    int n = idx >> 9, k = idx & 511;
    th[idx] = __float2half_rn(__ldg(W + (size_t)k * D_ + n));
}

// ---------------- cp.async double-buffered fp16 single-term GEMM ----------------
// Tile: M=128, N=128, k-stage 64. 256 threads (8 warps, 4 m-blocks x 2 n-blocks).
#define GA  0
#define GW  16384
#define GBUF 32768
#define GSMEM (2 * GBUF)   // 64 KB

// OUT: 0 = fp32, 2 = single rounded fp16
template <int OUT>
__device__ __forceinline__ void gemm_body(
    const __half* __restrict__ A1, const __half* __restrict__ Wt,
    float* __restrict__ Cf, __half* __restrict__ Ch,
    float alpha, char* smem, int m0, int n0)
{
    const uint32_t sb = smem_u32(smem);
    const int tid = threadIdx.x;
    const int w = tid >> 5;
    const int lane = tid & 31;
    const int group = lane >> 2, tig = lane & 3;
    const int m_ = lane >> 3, r_ = lane & 7;
    const int rsel = m_ >> 1, kodd = m_ & 1;
    const int wr = w >> 1;
    const int wc = w & 1;

    float cacc[2][8][4];
#pragma unroll
    for (int mt = 0; mt < 2; ++mt)
#pragma unroll
        for (int nt = 0; nt < 8; ++nt)
#pragma unroll
            for (int j = 0; j < 4; ++j) cacc[mt][nt][j] = 0.f;

    const int tok = tid >> 1, half_ = tid & 1;
    const uint32_t arow0 = (uint32_t)((wr * 32 + kodd * 8 + r_) * 128);
    const uint32_t arow1 = arow0 + 16 * 128;
    const uint32_t brow = (uint32_t)((wc * 64 + rsel * 8 + r_) * 128);

    auto issue = [&](int s, int buf) {
        const uint32_t bb = sb + buf * GBUF;
        const size_t abase = (size_t)(m0 + tok) * D_ + s * 64 + half_ * 32;
        const size_t wbase = (size_t)(n0 + tok) * D_ + s * 64 + half_ * 32;
#pragma unroll
        for (int i = 0; i < 4; ++i) {
            const int chunk = half_ * 4 + i;
            const uint32_t off = (uint32_t)(tok * 128 + ((chunk ^ (tok & 7)) << 4));
            CP16(bb + GA + off, A1 + abase + i * 8);
            CP16(bb + GW + off, Wt + wbase + i * 8);
        }
        CP_COMMIT();
    };

    issue(0, 0);

    for (int s = 0; s < D_ / 64; ++s) {
        if (s + 1 < D_ / 64) { issue(s + 1, (s + 1) & 1); CP_WAIT(1); }
        else                 { CP_WAIT(0); }
        __syncthreads();

        const uint32_t bb = sb + (s & 1) * GBUF;

#pragma unroll
        for (int ks = 0; ks < 4; ++ks) {
            const uint32_t aoff = (uint32_t)(((2 * ks + rsel) ^ r_) << 4);
            uint32_t ah0[4], ah1[4];
            ldmx4(ah0, bb + GA + arow0 + aoff);
            ldmx4(ah1, bb + GA + arow1 + aoff);
            const uint32_t csw = (uint32_t)(((2 * ks + kodd) ^ r_) << 4);
#pragma unroll
            for (int ntp = 0; ntp < 4; ++ntp) {
                uint32_t bh[4];
                ldmx4(bh, bb + GW + brow + (uint32_t)(ntp * 2048) + csw);
                mma_f16(cacc[0][2*ntp],     ah0, bh[0], bh[1]);
                mma_f16(cacc[0][2*ntp + 1], ah0, bh[2], bh[3]);
                mma_f16(cacc[1][2*ntp],     ah1, bh[0], bh[1]);
                mma_f16(cacc[1][2*ntp + 1], ah1, bh[2], bh[3]);
            }
        }
        __syncthreads();
    }

#pragma unroll
    for (int mt = 0; mt < 2; ++mt) {
        const size_t row = (size_t)(m0 + wr * 32 + mt * 16 + group);
#pragma unroll
        for (int nt = 0; nt < 8; ++nt) {
            const int col = n0 + wc * 64 + nt * 8 + 2 * tig;
            const float v0 = cacc[mt][nt][0] * alpha, v1 = cacc[mt][nt][1] * alpha;
            const float v2 = cacc[mt][nt][2] * alpha, v3 = cacc[mt][nt][3] * alpha;
            if (OUT == 2) {
                *(__half2*)(Ch + row * D_ + col) = __floats2half2_rn(v0, v1);
                *(__half2*)(Ch + (row + 8) * D_ + col) = __floats2half2_rn(v2, v3);
            } else {
                *(float2*)(Cf + row * D_ + col) = make_float2(v0, v1);
                *(float2*)(Cf + (row + 8) * D_ + col) = make_float2(v2, v3);
            }
        }
    }
}

__global__ __launch_bounds__(256, 2)
void gemm_qkv_kernel(const __half* __restrict__ x0, const __half* __restrict__ x1,
                     const __half* __restrict__ x2,
                     const __half* __restrict__ w0, const __half* __restrict__ w1,
                     const __half* __restrict__ w2,
                     __half* __restrict__ q1, __half* __restrict__ k1,
                     __half* __restrict__ v1)
{
    extern __shared__ char smem[];
    const int z = blockIdx.z;
    const int m0 = blockIdx.y * 128, n0 = blockIdx.x * 128;
    const float qalpha = 0.125f * 1.4426950408889634f;
    if (z == 0)
        gemm_body<2>(x0, w0, nullptr, q1, qalpha, smem, m0, n0);
    else if (z == 1)
        gemm_body<2>(x1, w1, nullptr, k1, 1.0f, smem, m0, n0);
    else
        gemm_body<2>(x2, w2, nullptr, v1, 1.0f, smem, m0, n0);
}

__global__ __launch_bounds__(256, 2)
void gemm_out_kernel(const __half* __restrict__ A1,
                     const __half* __restrict__ Wt, float* __restrict__ Cf)
{
    extern __shared__ char smem[];
    gemm_body<0>(A1, Wt, Cf, nullptr, 1.0f, smem,
                 blockIdx.y * 128, blockIdx.x * 128);
}

// ================= flash attention: 128 q rows/CTA, kv tile 128 =================
#define BK 0
#define BV 16384
#define BUF_SZ 32768
#define ATT_SMEM 65536
#define NTILES (S_ / 128)   // 16

__global__ __launch_bounds__(256, 2)
void attn_mma_kernel(const __half* __restrict__ Q1,
                     const __half* __restrict__ K1, const __half* __restrict__ V1,
                     __half* __restrict__ O1)
{
    extern __shared__ char smem[];
    const uint32_t sb = smem_u32(smem);
    const int tid = threadIdx.x;
    const int w = tid >> 5;
    const int lane = tid & 31;
    const int group = lane >> 2, tig = lane & 3;
    const int m_ = lane >> 3, r_ = lane & 7;
    const int rsel = m_ >> 1, kodd = m_ & 1;
    const int bh_ = blockIdx.y;
    const int b = bh_ >> 3, h = bh_ & 7;
    const int q0 = blockIdx.x * 128;

    const uint32_t krow = (uint32_t)((rsel * 8 + r_) * 128);
    const int stok = tid >> 1;          // 0..127 (token within kv tile)
    const int shalf = tid & 1;          // d-half
    const size_t kvbase = (size_t)(b * S_) * D_ + h * DH_;

    // ---- Q fragments (single fp16, pre-scaled by log2e/8) ----
    uint32_t qh[4][4];
    {
        const size_t qrow = (size_t)(b * S_ + q0 + w * 16 + group);
        const __half* qhp = Q1 + qrow * D_ + h * DH_;
#pragma unroll
        for (int ks = 0; ks < 4; ++ks) {
            const int c = ks * 16 + 2 * tig;
            qh[ks][0] = *(const uint32_t*)(qhp + c);
            qh[ks][1] = *(const uint32_t*)(qhp + 8 * D_ + c);
            qh[ks][2] = *(const uint32_t*)(qhp + c + 8);
            qh[ks][3] = *(const uint32_t*)(qhp + 8 * D_ + c + 8);
        }
    }

    float oacc[8][4];
#pragma unroll
    for (int i = 0; i < 8; ++i)
#pragma unroll
        for (int j = 0; j < 4; ++j) oacc[i][j] = 0.f;
    float lsum0 = 0.f, lsum1 = 0.f;

    // stage kv tile t (128 tokens x 64 d, K and V) into buffer buf
    auto issue_tile = [&](int t, int buf) {
        const size_t g = kvbase + (size_t)(t * 128 + stok) * D_ + shalf * 32;
        const uint32_t bufb = sb + buf * BUF_SZ;
#pragma unroll
        for (int i = 0; i < 4; ++i) {
            const int chunk = shalf * 4 + i;
            const uint32_t off = (uint32_t)(stok * 128 + ((chunk ^ (stok & 7)) << 4));
            CP16(bufb + BK + off, K1 + g + i * 8);
            CP16(bufb + BV + off, V1 + g + i * 8);
        }
        CP_COMMIT();
    };

    issue_tile(0, 0);

    for (int t = 0; t < NTILES; ++t) {
        if (t + 1 < NTILES) { issue_tile(t + 1, (t + 1) & 1); CP_WAIT(1); }
        else                { CP_WAIT(0); }
        __syncthreads();

        const uint32_t bufb = sb + (t & 1) * BUF_SZ;

#pragma unroll
        for (int ks2 = 0; ks2 < 8; ++ks2) {
            float sacc[2][4];
#pragma unroll
            for (int j = 0; j < 4; ++j) { sacc[0][j] = 0.f; sacc[1][j] = 0.f; }
            const uint32_t ntbase = (uint32_t)(ks2 * 2048);
#pragma unroll
            for (int ks = 0; ks < 4; ++ks) {
                const uint32_t csw = (uint32_t)(((2 * ks + kodd) ^ r_) << 4);
                uint32_t bhv[4];
                ldmx4(bhv, bufb + BK + krow + ntbase + csw);
                mma_f16(sacc[0], qh[ks], bhv[0], bhv[1]);
                mma_f16(sacc[1], qh[ks], bhv[2], bhv[3]);
            }
            const float p00 = ex2f(sacc[0][0]), p01 = ex2f(sacc[0][1]);
            const float p02 = ex2f(sacc[0][2]), p03 = ex2f(sacc[0][3]);
            const float p10 = ex2f(sacc[1][0]), p11 = ex2f(sacc[1][1]);
            const float p12 = ex2f(sacc[1][2]), p13 = ex2f(sacc[1][3]);
            lsum0 += p00 + p01 + p10 + p11;
            lsum1 += p02 + p03 + p12 + p13;
            uint32_t pha[4];
            pha[0] = pack2h(p00, p01);
            pha[1] = pack2h(p02, p03);
            pha[2] = pack2h(p10, p11);
            pha[3] = pack2h(p12, p13);

            const uint32_t vrow = (uint32_t)((ks2 * 16 + kodd * 8 + r_) * 128);
#pragma unroll
            for (int ntp = 0; ntp < 4; ++ntp) {
                const uint32_t csw = (uint32_t)(((2 * ntp + rsel) ^ r_) << 4);
                uint32_t bhv[4];
                ldmx4t(bhv, bufb + BV + vrow + csw);
                mma_f16(oacc[2*ntp],     pha, bhv[0], bhv[1]);
                mma_f16(oacc[2*ntp + 1], pha, bhv[2], bhv[3]);
            }
        }
        __syncthreads();
    }

    lsum0 += __shfl_xor_sync(0xffffffffu, lsum0, 1);
    lsum0 += __shfl_xor_sync(0xffffffffu, lsum0, 2);
    lsum1 += __shfl_xor_sync(0xffffffffu, lsum1, 1);
    lsum1 += __shfl_xor_sync(0xffffffffu, lsum1, 2);
    const float inv0 = 1.f / lsum0;
    const float inv1 = 1.f / lsum1;

    const size_t orow = (size_t)(b * S_ + q0 + w * 16 + group);
#pragma unroll
    for (int nt = 0; nt < 8; ++nt) {
        const int col = h * DH_ + nt * 8 + 2 * tig;
        *(__half2*)(O1 + orow * D_ + col) =
            __floats2half2_rn(oacc[nt][0] * inv0, oacc[nt][1] * inv0);
        *(__half2*)(O1 + (orow + 8) * D_ + col) =
            __floats2half2_rn(oacc[nt][2] * inv1, oacc[nt][3] * inv1);
    }
}

// ---------------- launch ----------------
extern "C" void kernel_launch(void* const* d_in, const int* in_sizes, int n_in,
                              void* d_out, int out_size)
{
    const float* xq = (const float*)d_in[0];
    const float* xk = (const float*)d_in[1];
    const float* xv = (const float*)d_in[2];
    const float* Wq = (const float*)d_in[3];
    const float* Wk = (const float*)d_in[4];
    const float* Wv = (const float*)d_in[5];
    const float* Wo = (const float*)d_in[6];
    float* out = (float*)d_out;

    void *x0, *x1, *x2, *q1, *k1, *v1, *o1;
    void *w0, *w1, *w2, *w3;
    cudaGetSymbolAddress(&x0, g_x0);
    cudaGetSymbolAddress(&x1, g_x1);
    cudaGetSymbolAddress(&x2, g_x2);
    cudaGetSymbolAddress(&q1, g_q1);
    cudaGetSymbolAddress(&k1, g_k1);
    cudaGetSymbolAddress(&v1, g_v1);
    cudaGetSymbolAddress(&o1, g_o1);
    cudaGetSymbolAddress(&w0, g_w0);
    cudaGetSymbolAddress(&w1, g_w1);
    cudaGetSymbolAddress(&w2, g_w2);
    cudaGetSymbolAddress(&w3, g_w3);

    static int init_done = 0;
    if (!init_done) {
        cudaFuncSetAttribute(attn_mma_kernel, cudaFuncAttributeMaxDynamicSharedMemorySize, ATT_SMEM);
        cudaFuncSetAttribute(gemm_qkv_kernel, cudaFuncAttributeMaxDynamicSharedMemorySize, GSMEM);
        cudaFuncSetAttribute(gemm_out_kernel, cudaFuncAttributeMaxDynamicSharedMemorySize, GSMEM);
        init_done = 1;
    }

    typedef __half hf;

    // prep: round activations to fp16 (single); transpose+round weights
    dim3 agrid_s((M_ * D_ / 4) / 256, 3);
    round_act3_kernel<<<agrid_s, 256>>>(xq, xk, xv, (hf*)x0, (hf*)x1, (hf*)x2);
    dim3 wgrid((D_ * D_) / 256, 4);
    split_w4_kernel<<<wgrid, 256>>>(Wq, Wk, Wv, Wo,
                                    (hf*)w0, (hf*)w1, (hf*)w2, (hf*)w3);

    // merged Q/K/V projections (single-term A)
    dim3 qkvgrid(D_ / 128, M_ / 128, 3);   // (4, 64, 3)
    gemm_qkv_kernel<<<qkvgrid, 256, GSMEM>>>(
        (hf*)x0, (hf*)x1, (hf*)x2,
        (hf*)w0, (hf*)w1, (hf*)w2,
        (hf*)q1, (hf*)k1, (hf*)v1);

    // attention (kv tile 128)
    dim3 agrid(S_ / 128, B_ * H_);   // (16, 32)
    attn_mma_kernel<<<agrid, 256, ATT_SMEM>>>((hf*)q1, (hf*)k1, (hf*)v1, (hf*)o1);

    // output projection (single-term A, fp32 out)
    dim3 ogrid(D_ / 128, M_ / 128);   // (4, 64)
    gemm_out_kernel<<<ogrid, 256, GSMEM>>>((hf*)o1, (hf*)w3, out);
}

// round 16
// speedup vs baseline: 1.2801x; 1.1228x over previous
#include <cuda_runtime.h>
#include <cuda_fp16.h>
#include <math.h>
#include <stdint.h>

#define B_ 4
#define S_ 2048
#define D_ 512
#define H_ 8
#define DH_ 64
#define M_ (B_ * S_)   // 8192

// ---------------- scratch (device globals; no allocation allowed) ----------------
__device__ __half g_x0[(size_t)M_ * D_];
__device__ __half g_x1[(size_t)M_ * D_];
__device__ __half g_x2[(size_t)M_ * D_];
__device__ __half g_q1[(size_t)M_ * D_];
__device__ __half g_k1[(size_t)M_ * D_];
__device__ __half g_v1[(size_t)M_ * D_];
__device__ __half g_o1[(size_t)M_ * D_];
__device__ __half g_w0[(size_t)D_ * D_];
__device__ __half g_w1[(size_t)D_ * D_];
__device__ __half g_w2[(size_t)D_ * D_];
__device__ __half g_w3[(size_t)D_ * D_];

// ================= helpers =================
__device__ __forceinline__ uint32_t smem_u32(const void* p) {
    uint32_t a;
    asm("{ .reg .u64 t; cvta.to.shared.u64 t, %1; cvt.u32.u64 %0, t; }" : "=r"(a) : "l"(p));
    return a;
}
__device__ __forceinline__ uint32_t pack2h(float a, float b) {
    __half2 v = __floats2half2_rn(a, b);
    return *reinterpret_cast<uint32_t*>(&v);
}
__device__ __forceinline__ float ex2f(float x) {
    float r;
    asm("ex2.approx.f32 %0, %1;" : "=f"(r) : "f"(x));
    return r;
}
__device__ __forceinline__ void mma_f16(float* c, const uint32_t* a,
                                        uint32_t b0, uint32_t b1) {
    asm volatile(
        "mma.sync.aligned.m16n8k16.row.col.f32.f16.f16.f32 "
        "{%0,%1,%2,%3}, {%4,%5,%6,%7}, {%8,%9}, {%0,%1,%2,%3};"
        : "+f"(c[0]), "+f"(c[1]), "+f"(c[2]), "+f"(c[3])
        : "r"(a[0]), "r"(a[1]), "r"(a[2]), "r"(a[3]), "r"(b0), "r"(b1));
}
__device__ __forceinline__ void ldmx4(uint32_t* r, uint32_t addr) {
    asm volatile("ldmatrix.sync.aligned.m8n8.x4.shared.b16 {%0,%1,%2,%3}, [%4];"
                 : "=r"(r[0]), "=r"(r[1]), "=r"(r[2]), "=r"(r[3]) : "r"(addr));
}
__device__ __forceinline__ void ldmx4t(uint32_t* r, uint32_t addr) {
    asm volatile("ldmatrix.sync.aligned.m8n8.x4.trans.shared.b16 {%0,%1,%2,%3}, [%4];"
                 : "=r"(r[0]), "=r"(r[1]), "=r"(r[2]), "=r"(r[3]) : "r"(addr));
}
#define CP16(dst, src) \
    asm volatile("cp.async.cg.shared.global [%0], [%1], 16;" :: "r"(dst), "l"(src) : "memory")
#define CP_COMMIT() asm volatile("cp.async.commit_group;" ::: "memory")
#define CP_WAIT(n)  asm volatile("cp.async.wait_group %0;" :: "n"(n) : "memory")

// ---------------- prep: one launch (y 0-2: activations, y 3-6: weights) ----------------
__global__ void prep_kernel(const float* __restrict__ X0, const float* __restrict__ X1,
                            const float* __restrict__ X2,
                            const float* __restrict__ W0, const float* __restrict__ W1,
                            const float* __restrict__ W2, const float* __restrict__ W3,
                            __half* __restrict__ y0, __half* __restrict__ y1,
                            __half* __restrict__ y2,
                            __half* __restrict__ t0, __half* __restrict__ t1,
                            __half* __restrict__ t2, __half* __restrict__ t3)
{
    const int which = blockIdx.y;
    if (which < 3) {
        const float* X = (which == 0) ? X0 : (which == 1) ? X1 : X2;
        __half* Y = (which == 0) ? y0 : (which == 1) ? y1 : y2;
        size_t i = (size_t)blockIdx.x * blockDim.x + threadIdx.x;   // float4 index
        float4 v = __ldg((const float4*)X + i);
        ((uint2*)Y)[i] = make_uint2(pack2h(v.x, v.y), pack2h(v.z, v.w));
    } else {
        if (blockIdx.x >= (D_ * D_) / 256) return;
        const int wsel = which - 3;
        const float* W = (wsel == 0) ? W0 : (wsel == 1) ? W1 : (wsel == 2) ? W2 : W3;
        __half* th = (wsel == 0) ? t0 : (wsel == 1) ? t1 : (wsel == 2) ? t2 : t3;
        int idx = blockIdx.x * blockDim.x + threadIdx.x;  // n*512 + k
        int n = idx >> 9, k = idx & 511;
        th[idx] = __float2half_rn(__ldg(W + (size_t)k * D_ + n));
    }
}

// ---------------- cp.async double-buffered fp16 single-term GEMM ----------------
// Tile: M=128, N=128, k-stage 64. 256 threads (8 warps, 4 m-blocks x 2 n-blocks).
#define GA  0
#define GW  16384
#define GBUF 32768
#define GSMEM (2 * GBUF)   // 64 KB

// OUT: 0 = fp32, 2 = single rounded fp16
template <int OUT>
__device__ __forceinline__ void gemm_body(
    const __half* __restrict__ A1, const __half* __restrict__ Wt,
    float* __restrict__ Cf, __half* __restrict__ Ch,
    float alpha, char* smem, int m0, int n0)
{
    const uint32_t sb = smem_u32(smem);
    const int tid = threadIdx.x;
    const int w = tid >> 5;
    const int lane = tid & 31;
    const int group = lane >> 2, tig = lane & 3;
    const int m_ = lane >> 3, r_ = lane & 7;
    const int rsel = m_ >> 1, kodd = m_ & 1;
    const int wr = w >> 1;
    const int wc = w & 1;

    float cacc[2][8][4];
#pragma unroll
    for (int mt = 0; mt < 2; ++mt)
#pragma unroll
        for (int nt = 0; nt < 8; ++nt)
#pragma unroll
            for (int j = 0; j < 4; ++j) cacc[mt][nt][j] = 0.f;

    const int tok = tid >> 1, half_ = tid & 1;
    const uint32_t arow0 = (uint32_t)((wr * 32 + kodd * 8 + r_) * 128);
    const uint32_t arow1 = arow0 + 16 * 128;
    const uint32_t brow = (uint32_t)((wc * 64 + rsel * 8 + r_) * 128);

    auto issue = [&](int s, int buf) {
        const uint32_t bb = sb + buf * GBUF;
        const size_t abase = (size_t)(m0 + tok) * D_ + s * 64 + half_ * 32;
        const size_t wbase = (size_t)(n0 + tok) * D_ + s * 64 + half_ * 32;
#pragma unroll
        for (int i = 0; i < 4; ++i) {
            const int chunk = half_ * 4 + i;
            const uint32_t off = (uint32_t)(tok * 128 + ((chunk ^ (tok & 7)) << 4));
            CP16(bb + GA + off, A1 + abase + i * 8);
            CP16(bb + GW + off, Wt + wbase + i * 8);
        }
        CP_COMMIT();
    };

    issue(0, 0);

    for (int s = 0; s < D_ / 64; ++s) {
        if (s + 1 < D_ / 64) { issue(s + 1, (s + 1) & 1); CP_WAIT(1); }
        else                 { CP_WAIT(0); }
        __syncthreads();

        const uint32_t bb = sb + (s & 1) * GBUF;

#pragma unroll
        for (int ks = 0; ks < 4; ++ks) {
            const uint32_t aoff = (uint32_t)(((2 * ks + rsel) ^ r_) << 4);
            uint32_t ah0[4], ah1[4];
            ldmx4(ah0, bb + GA + arow0 + aoff);
            ldmx4(ah1, bb + GA + arow1 + aoff);
            const uint32_t csw = (uint32_t)(((2 * ks + kodd) ^ r_) << 4);
#pragma unroll
            for (int ntp = 0; ntp < 4; ++ntp) {
                uint32_t bh[4];
                ldmx4(bh, bb + GW + brow + (uint32_t)(ntp * 2048) + csw);
                mma_f16(cacc[0][2*ntp],     ah0, bh[0], bh[1]);
                mma_f16(cacc[0][2*ntp + 1], ah0, bh[2], bh[3]);
                mma_f16(cacc[1][2*ntp],     ah1, bh[0], bh[1]);
                mma_f16(cacc[1][2*ntp + 1], ah1, bh[2], bh[3]);
            }
        }
        __syncthreads();
    }

#pragma unroll
    for (int mt = 0; mt < 2; ++mt) {
        const size_t row = (size_t)(m0 + wr * 32 + mt * 16 + group);
#pragma unroll
        for (int nt = 0; nt < 8; ++nt) {
            const int col = n0 + wc * 64 + nt * 8 + 2 * tig;
            const float v0 = cacc[mt][nt][0] * alpha, v1 = cacc[mt][nt][1] * alpha;
            const float v2 = cacc[mt][nt][2] * alpha, v3 = cacc[mt][nt][3] * alpha;
            if (OUT == 2) {
                *(__half2*)(Ch + row * D_ + col) = __floats2half2_rn(v0, v1);
                *(__half2*)(Ch + (row + 8) * D_ + col) = __floats2half2_rn(v2, v3);
            } else {
                *(float2*)(Cf + row * D_ + col) = make_float2(v0, v1);
                *(float2*)(Cf + (row + 8) * D_ + col) = make_float2(v2, v3);
            }
        }
    }
}

__global__ __launch_bounds__(256, 2)
void gemm_qkv_kernel(const __half* __restrict__ x0, const __half* __restrict__ x1,
                     const __half* __restrict__ x2,
                     const __half* __restrict__ w0, const __half* __restrict__ w1,
                     const __half* __restrict__ w2,
                     __half* __restrict__ q1, __half* __restrict__ k1,
                     __half* __restrict__ v1)
{
    extern __shared__ char smem[];
    const int z = blockIdx.z;
    const int m0 = blockIdx.y * 128, n0 = blockIdx.x * 128;
    const float qalpha = 0.125f * 1.4426950408889634f;
    if (z == 0)
        gemm_body<2>(x0, w0, nullptr, q1, qalpha, smem, m0, n0);
    else if (z == 1)
        gemm_body<2>(x1, w1, nullptr, k1, 1.0f, smem, m0, n0);
    else
        gemm_body<2>(x2, w2, nullptr, v1, 1.0f, smem, m0, n0);
}

__global__ __launch_bounds__(256, 2)
void gemm_out_kernel(const __half* __restrict__ A1,
                     const __half* __restrict__ Wt, float* __restrict__ Cf)
{
    extern __shared__ char smem[];
    gemm_body<0>(A1, Wt, Cf, nullptr, 1.0f, smem,
                 blockIdx.y * 128, blockIdx.x * 128);
}

// ================= flash attention (R14 config: kv tile 64) =================
#define BK 0
#define BV 8192
#define BUF_SZ 16384
#define ATT_SMEM 32768
#define NTILES (S_ / 64)   // 32

__global__ __launch_bounds__(256, 2)
void attn_mma_kernel(const __half* __restrict__ Q1,
                     const __half* __restrict__ K1, const __half* __restrict__ V1,
                     __half* __restrict__ O1)
{
    extern __shared__ char smem[];
    const uint32_t sb = smem_u32(smem);
    const int tid = threadIdx.x;
    const int w = tid >> 5;
    const int lane = tid & 31;
    const int group = lane >> 2, tig = lane & 3;
    const int m_ = lane >> 3, r_ = lane & 7;
    const int rsel = m_ >> 1, kodd = m_ & 1;
    const int bh_ = blockIdx.y;
    const int b = bh_ >> 3, h = bh_ & 7;
    const int q0 = blockIdx.x * 128;

    const uint32_t krow = (uint32_t)((rsel * 8 + r_) * 128);
    const int stok = tid >> 2;
    const int sc0 = (tid & 3) * 2;
    const size_t kvbase = (size_t)(b * S_) * D_ + h * DH_;

    // ---- Q fragments (single fp16, pre-scaled by log2e/8) ----
    uint32_t qh[4][4];
    {
        const size_t qrow = (size_t)(b * S_ + q0 + w * 16 + group);
        const __half* qhp = Q1 + qrow * D_ + h * DH_;
#pragma unroll
        for (int ks = 0; ks < 4; ++ks) {
            const int c = ks * 16 + 2 * tig;
            qh[ks][0] = *(const uint32_t*)(qhp + c);
            qh[ks][1] = *(const uint32_t*)(qhp + 8 * D_ + c);
            qh[ks][2] = *(const uint32_t*)(qhp + c + 8);
            qh[ks][3] = *(const uint32_t*)(qhp + 8 * D_ + c + 8);
        }
    }

    float oacc[8][4];
#pragma unroll
    for (int i = 0; i < 8; ++i)
#pragma unroll
        for (int j = 0; j < 4; ++j) oacc[i][j] = 0.f;
    float lsum0 = 0.f, lsum1 = 0.f;

    auto issue_tile = [&](int t, int buf) {
        const size_t g = kvbase + (size_t)(t * 64 + stok) * D_;
        const uint32_t bufb = sb + buf * BUF_SZ;
#pragma unroll
        for (int i = 0; i < 2; ++i) {
            const int c = sc0 + i;
            const uint32_t off = (uint32_t)(stok * 128 + ((c ^ (stok & 7)) << 4));
            const size_t ge = g + c * 8;
            CP16(bufb + BK + off, K1 + ge);
            CP16(bufb + BV + off, V1 + ge);
        }
        CP_COMMIT();
    };

    issue_tile(0, 0);

    for (int t = 0; t < NTILES; ++t) {
        if (t + 1 < NTILES) { issue_tile(t + 1, (t + 1) & 1); CP_WAIT(1); }
        else                { CP_WAIT(0); }
        __syncthreads();

        const uint32_t bufb = sb + (t & 1) * BUF_SZ;

#pragma unroll
        for (int ks2 = 0; ks2 < 4; ++ks2) {
            float sacc[2][4];
#pragma unroll
            for (int j = 0; j < 4; ++j) { sacc[0][j] = 0.f; sacc[1][j] = 0.f; }
            const uint32_t ntbase = (uint32_t)(ks2 * 2048);
#pragma unroll
            for (int ks = 0; ks < 4; ++ks) {
                const uint32_t csw = (uint32_t)(((2 * ks + kodd) ^ r_) << 4);
                uint32_t bhv[4];
                ldmx4(bhv, bufb + BK + krow + ntbase + csw);
                mma_f16(sacc[0], qh[ks], bhv[0], bhv[1]);
                mma_f16(sacc[1], qh[ks], bhv[2], bhv[3]);
            }
            const float p00 = ex2f(sacc[0][0]), p01 = ex2f(sacc[0][1]);
            const float p02 = ex2f(sacc[0][2]), p03 = ex2f(sacc[0][3]);
            const float p10 = ex2f(sacc[1][0]), p11 = ex2f(sacc[1][1]);
            const float p12 = ex2f(sacc[1][2]), p13 = ex2f(sacc[1][3]);
            lsum0 += p00 + p01 + p10 + p11;
            lsum1 += p02 + p03 + p12 + p13;
            uint32_t pha[4];
            pha[0] = pack2h(p00, p01);
            pha[1] = pack2h(p02, p03);
            pha[2] = pack2h(p10, p11);
            pha[3] = pack2h(p12, p13);

            const uint32_t vrow = (uint32_t)((ks2 * 16 + kodd * 8 + r_) * 128);
#pragma unroll
            for (int ntp = 0; ntp < 4; ++ntp) {
                const uint32_t csw = (uint32_t)(((2 * ntp + rsel) ^ r_) << 4);
                uint32_t bhv[4];
                ldmx4t(bhv, bufb + BV + vrow + csw);
                mma_f16(oacc[2*ntp],     pha, bhv[0], bhv[1]);
                mma_f16(oacc[2*ntp + 1], pha, bhv[2], bhv[3]);
            }
        }
        __syncthreads();
    }

    lsum0 += __shfl_xor_sync(0xffffffffu, lsum0, 1);
    lsum0 += __shfl_xor_sync(0xffffffffu, lsum0, 2);
    lsum1 += __shfl_xor_sync(0xffffffffu, lsum1, 1);
    lsum1 += __shfl_xor_sync(0xffffffffu, lsum1, 2);
    const float inv0 = 1.f / lsum0;
    const float inv1 = 1.f / lsum1;

    const size_t orow = (size_t)(b * S_ + q0 + w * 16 + group);
#pragma unroll
    for (int nt = 0; nt < 8; ++nt) {
        const int col = h * DH_ + nt * 8 + 2 * tig;
        *(__half2*)(O1 + orow * D_ + col) =
            __floats2half2_rn(oacc[nt][0] * inv0, oacc[nt][1] * inv0);
        *(__half2*)(O1 + (orow + 8) * D_ + col) =
            __floats2half2_rn(oacc[nt][2] * inv1, oacc[nt][3] * inv1);
    }
}

// ---------------- launch ----------------
extern "C" void kernel_launch(void* const* d_in, const int* in_sizes, int n_in,
                              void* d_out, int out_size)
{
    const float* xq = (const float*)d_in[0];
    const float* xk = (const float*)d_in[1];
    const float* xv = (const float*)d_in[2];
    const float* Wq = (const float*)d_in[3];
    const float* Wk = (const float*)d_in[4];
    const float* Wv = (const float*)d_in[5];
    const float* Wo = (const float*)d_in[6];
    float* out = (float*)d_out;

    void *x0, *x1, *x2, *q1, *k1, *v1, *o1;
    void *w0, *w1, *w2, *w3;
    cudaGetSymbolAddress(&x0, g_x0);
    cudaGetSymbolAddress(&x1, g_x1);
    cudaGetSymbolAddress(&x2, g_x2);
    cudaGetSymbolAddress(&q1, g_q1);
    cudaGetSymbolAddress(&k1, g_k1);
    cudaGetSymbolAddress(&v1, g_v1);
    cudaGetSymbolAddress(&o1, g_o1);
    cudaGetSymbolAddress(&w0, g_w0);
    cudaGetSymbolAddress(&w1, g_w1);
    cudaGetSymbolAddress(&w2, g_w2);
    cudaGetSymbolAddress(&w3, g_w3);

    static int init_done = 0;
    if (!init_done) {
        cudaFuncSetAttribute(attn_mma_kernel, cudaFuncAttributeMaxDynamicSharedMemorySize, ATT_SMEM);
        cudaFuncSetAttribute(gemm_qkv_kernel, cudaFuncAttributeMaxDynamicSharedMemorySize, GSMEM);
        cudaFuncSetAttribute(gemm_out_kernel, cudaFuncAttributeMaxDynamicSharedMemorySize, GSMEM);
        init_done = 1;
    }

    typedef __half hf;

    // prep: single launch (activations + weights)
    dim3 pgrid((M_ * D_ / 4) / 256, 7);
    prep_kernel<<<pgrid, 256>>>(xq, xk, xv, Wq, Wk, Wv, Wo,
                                (hf*)x0, (hf*)x1, (hf*)x2,
                                (hf*)w0, (hf*)w1, (hf*)w2, (hf*)w3);

    // merged Q/K/V projections (single-term A)
    dim3 qkvgrid(D_ / 128, M_ / 128, 3);   // (4, 64, 3)
    gemm_qkv_kernel<<<qkvgrid, 256, GSMEM>>>(
        (hf*)x0, (hf*)x1, (hf*)x2,
        (hf*)w0, (hf*)w1, (hf*)w2,
        (hf*)q1, (hf*)k1, (hf*)v1);

    // attention (kv tile 64)
    dim3 agrid(S_ / 128, B_ * H_);   // (16, 32)
    attn_mma_kernel<<<agrid, 256, ATT_SMEM>>>((hf*)q1, (hf*)k1, (hf*)v1, (hf*)o1);

    // output projection (single-term A, fp32 out)
    dim3 ogrid(D_ / 128, M_ / 128);   // (4, 64)
    gemm_out_kernel<<<ogrid, 256, GSMEM>>>((hf*)o1, (hf*)w3, out);
}

// round 17
// speedup vs baseline: 1.3139x; 1.0264x over previous
#include <cuda_runtime.h>
#include <cuda_fp16.h>
#include <math.h>
#include <stdint.h>

#define B_ 4
#define S_ 2048
#define D_ 512
#define H_ 8
#define DH_ 64
#define M_ (B_ * S_)   // 8192

// ---------------- scratch (device globals; no allocation allowed) ----------------
__device__ __half g_x0[(size_t)M_ * D_];
__device__ __half g_x1[(size_t)M_ * D_];
__device__ __half g_x2[(size_t)M_ * D_];
__device__ __half g_q1[(size_t)M_ * D_];
__device__ __half g_k1[(size_t)M_ * D_];
__device__ __half g_v1[(size_t)M_ * D_];
__device__ __half g_o1[(size_t)M_ * D_];
__device__ __half g_w0[(size_t)D_ * D_];
__device__ __half g_w1[(size_t)D_ * D_];
__device__ __half g_w2[(size_t)D_ * D_];
__device__ __half g_w3[(size_t)D_ * D_];

// ================= helpers =================
__device__ __forceinline__ uint32_t smem_u32(const void* p) {
    uint32_t a;
    asm("{ .reg .u64 t; cvta.to.shared.u64 t, %1; cvt.u32.u64 %0, t; }" : "=r"(a) : "l"(p));
    return a;
}
__device__ __forceinline__ uint32_t pack2h(float a, float b) {
    __half2 v = __floats2half2_rn(a, b);
    return *reinterpret_cast<uint32_t*>(&v);
}
__device__ __forceinline__ float ex2f(float x) {
    float r;
    asm("ex2.approx.f32 %0, %1;" : "=f"(r) : "f"(x));
    return r;
}
__device__ __forceinline__ void mma_f16(float* c, const uint32_t* a,
                                        uint32_t b0, uint32_t b1) {
    asm volatile(
        "mma.sync.aligned.m16n8k16.row.col.f32.f16.f16.f32 "
        "{%0,%1,%2,%3}, {%4,%5,%6,%7}, {%8,%9}, {%0,%1,%2,%3};"
        : "+f"(c[0]), "+f"(c[1]), "+f"(c[2]), "+f"(c[3])
        : "r"(a[0]), "r"(a[1]), "r"(a[2]), "r"(a[3]), "r"(b0), "r"(b1));
}
__device__ __forceinline__ void ldmx4(uint32_t* r, uint32_t addr) {
    asm volatile("ldmatrix.sync.aligned.m8n8.x4.shared.b16 {%0,%1,%2,%3}, [%4];"
                 : "=r"(r[0]), "=r"(r[1]), "=r"(r[2]), "=r"(r[3]) : "r"(addr));
}
__device__ __forceinline__ void ldmx4t(uint32_t* r, uint32_t addr) {
    asm volatile("ldmatrix.sync.aligned.m8n8.x4.trans.shared.b16 {%0,%1,%2,%3}, [%4];"
                 : "=r"(r[0]), "=r"(r[1]), "=r"(r[2]), "=r"(r[3]) : "r"(addr));
}
#define CP16(dst, src) \
    asm volatile("cp.async.cg.shared.global [%0], [%1], 16;" :: "r"(dst), "l"(src) : "memory")
#define CP_COMMIT() asm volatile("cp.async.commit_group;" ::: "memory")
#define CP_WAIT(n)  asm volatile("cp.async.wait_group %0;" :: "n"(n) : "memory")

#define ONES_H2 0x3C003C00u   // fp16 (1.0, 1.0)

// ---------------- prep: one launch (y 0-2: activations, y 3-6: weights) ----------------
__global__ void prep_kernel(const float* __restrict__ X0, const float* __restrict__ X1,
                            const float* __restrict__ X2,
                            const float* __restrict__ W0, const float* __restrict__ W1,
                            const float* __restrict__ W2, const float* __restrict__ W3,
                            __half* __restrict__ y0, __half* __restrict__ y1,
                            __half* __restrict__ y2,
                            __half* __restrict__ t0, __half* __restrict__ t1,
                            __half* __restrict__ t2, __half* __restrict__ t3)
{
    const int which = blockIdx.y;
    if (which < 3) {
        const float* X = (which == 0) ? X0 : (which == 1) ? X1 : X2;
        __half* Y = (which == 0) ? y0 : (which == 1) ? y1 : y2;
        size_t i = (size_t)blockIdx.x * blockDim.x + threadIdx.x;   // float4 index
        float4 v = __ldg((const float4*)X + i);
        ((uint2*)Y)[i] = make_uint2(pack2h(v.x, v.y), pack2h(v.z, v.w));
    } else {
        if (blockIdx.x >= (D_ * D_) / 256) return;
        const int wsel = which - 3;
        const float* W = (wsel == 0) ? W0 : (wsel == 1) ? W1 : (wsel == 2) ? W2 : W3;
        __half* th = (wsel == 0) ? t0 : (wsel == 1) ? t1 : (wsel == 2) ? t2 : t3;
        int idx = blockIdx.x * blockDim.x + threadIdx.x;  // n*512 + k
        int n = idx >> 9, k = idx & 511;
        th[idx] = __float2half_rn(__ldg(W + (size_t)k * D_ + n));
    }
}

// ---------------- cp.async triple-buffered fp16 single-term GEMM ----------------
// Tile: M=128, N=128, k-stage 64. 256 threads. 3 smem buffers, 1 sync/stage.
#define GA  0
#define GW  16384
#define GBUF 32768
#define GSMEM (3 * GBUF)   // 96 KB
#define GSTAGES (D_ / 64)  // 8

// OUT: 0 = fp32, 2 = single rounded fp16
template <int OUT>
__device__ __forceinline__ void gemm_body(
    const __half* __restrict__ A1, const __half* __restrict__ Wt,
    float* __restrict__ Cf, __half* __restrict__ Ch,
    float alpha, char* smem, int m0, int n0)
{
    const uint32_t sb = smem_u32(smem);
    const int tid = threadIdx.x;
    const int w = tid >> 5;
    const int lane = tid & 31;
    const int group = lane >> 2, tig = lane & 3;
    const int m_ = lane >> 3, r_ = lane & 7;
    const int rsel = m_ >> 1, kodd = m_ & 1;
    const int wr = w >> 1;
    const int wc = w & 1;

    float cacc[2][8][4];
#pragma unroll
    for (int mt = 0; mt < 2; ++mt)
#pragma unroll
        for (int nt = 0; nt < 8; ++nt)
#pragma unroll
            for (int j = 0; j < 4; ++j) cacc[mt][nt][j] = 0.f;

    const int tok = tid >> 1, half_ = tid & 1;
    const uint32_t arow0 = (uint32_t)((wr * 32 + kodd * 8 + r_) * 128);
    const uint32_t arow1 = arow0 + 16 * 128;
    const uint32_t brow = (uint32_t)((wc * 64 + rsel * 8 + r_) * 128);

    auto issue = [&](int s) {
        const uint32_t bb = sb + (uint32_t)(s % 3) * GBUF;
        const size_t abase = (size_t)(m0 + tok) * D_ + s * 64 + half_ * 32;
        const size_t wbase = (size_t)(n0 + tok) * D_ + s * 64 + half_ * 32;
#pragma unroll
        for (int i = 0; i < 4; ++i) {
            const int chunk = half_ * 4 + i;
            const uint32_t off = (uint32_t)(tok * 128 + ((chunk ^ (tok & 7)) << 4));
            CP16(bb + GA + off, A1 + abase + i * 8);
            CP16(bb + GW + off, Wt + wbase + i * 8);
        }
        CP_COMMIT();
    };

    issue(0);
    issue(1);

    for (int s = 0; s < GSTAGES; ++s) {
        CP_WAIT(1);
        __syncthreads();
        if (s + 2 < GSTAGES) issue(s + 2);
        else { CP_COMMIT(); }   // keep group count in sync for CP_WAIT semantics

        const uint32_t bb = sb + (uint32_t)(s % 3) * GBUF;

#pragma unroll
        for (int ks = 0; ks < 4; ++ks) {
            const uint32_t aoff = (uint32_t)(((2 * ks + rsel) ^ r_) << 4);
            uint32_t ah0[4], ah1[4];
            ldmx4(ah0, bb + GA + arow0 + aoff);
            ldmx4(ah1, bb + GA + arow1 + aoff);
            const uint32_t csw = (uint32_t)(((2 * ks + kodd) ^ r_) << 4);
#pragma unroll
            for (int ntp = 0; ntp < 4; ++ntp) {
                uint32_t bh[4];
                ldmx4(bh, bb + GW + brow + (uint32_t)(ntp * 2048) + csw);
                mma_f16(cacc[0][2*ntp],     ah0, bh[0], bh[1]);
                mma_f16(cacc[0][2*ntp + 1], ah0, bh[2], bh[3]);
                mma_f16(cacc[1][2*ntp],     ah1, bh[0], bh[1]);
                mma_f16(cacc[1][2*ntp + 1], ah1, bh[2], bh[3]);
            }
        }
    }

#pragma unroll
    for (int mt = 0; mt < 2; ++mt) {
        const size_t row = (size_t)(m0 + wr * 32 + mt * 16 + group);
#pragma unroll
        for (int nt = 0; nt < 8; ++nt) {
            const int col = n0 + wc * 64 + nt * 8 + 2 * tig;
            const float v0 = cacc[mt][nt][0] * alpha, v1 = cacc[mt][nt][1] * alpha;
            const float v2 = cacc[mt][nt][2] * alpha, v3 = cacc[mt][nt][3] * alpha;
            if (OUT == 2) {
                *(__half2*)(Ch + row * D_ + col) = __floats2half2_rn(v0, v1);
                *(__half2*)(Ch + (row + 8) * D_ + col) = __floats2half2_rn(v2, v3);
            } else {
                *(float2*)(Cf + row * D_ + col) = make_float2(v0, v1);
                *(float2*)(Cf + (row + 8) * D_ + col) = make_float2(v2, v3);
            }
        }
    }
}

__global__ __launch_bounds__(256, 2)
void gemm_qkv_kernel(const __half* __restrict__ x0, const __half* __restrict__ x1,
                     const __half* __restrict__ x2,
                     const __half* __restrict__ w0, const __half* __restrict__ w1,
                     const __half* __restrict__ w2,
                     __half* __restrict__ q1, __half* __restrict__ k1,
                     __half* __restrict__ v1)
{
    extern __shared__ char smem[];
    const int z = blockIdx.z;
    const int m0 = blockIdx.y * 128, n0 = blockIdx.x * 128;
    const float qalpha = 0.125f * 1.4426950408889634f;
    if (z == 0)
        gemm_body<2>(x0, w0, nullptr, q1, qalpha, smem, m0, n0);
    else if (z == 1)
        gemm_body<2>(x1, w1, nullptr, k1, 1.0f, smem, m0, n0);
    else
        gemm_body<2>(x2, w2, nullptr, v1, 1.0f, smem, m0, n0);
}

__global__ __launch_bounds__(256, 2)
void gemm_out_kernel(const __half* __restrict__ A1,
                     const __half* __restrict__ Wt, float* __restrict__ Cf)
{
    extern __shared__ char smem[];
    gemm_body<0>(A1, Wt, Cf, nullptr, 1.0f, smem,
                 blockIdx.y * 128, blockIdx.x * 128);
}

// ================= flash attention: kv tile 64, 3 buffers, ones-MMA lsum =================
#define BK 0
#define BV 8192
#define BUF_SZ 16384
#define ATT_SMEM (3 * BUF_SZ)   // 48 KB
#define NTILES (S_ / 64)        // 32

__global__ __launch_bounds__(256, 2)
void attn_mma_kernel(const __half* __restrict__ Q1,
                     const __half* __restrict__ K1, const __half* __restrict__ V1,
                     __half* __restrict__ O1)
{
    extern __shared__ char smem[];
    const uint32_t sb = smem_u32(smem);
    const int tid = threadIdx.x;
    const int w = tid >> 5;
    const int lane = tid & 31;
    const int group = lane >> 2, tig = lane & 3;
    const int m_ = lane >> 3, r_ = lane & 7;
    const int rsel = m_ >> 1, kodd = m_ & 1;
    const int bh_ = blockIdx.y;
    const int b = bh_ >> 3, h = bh_ & 7;
    const int q0 = blockIdx.x * 128;

    const uint32_t krow = (uint32_t)((rsel * 8 + r_) * 128);
    const int stok = tid >> 2;
    const int sc0 = (tid & 3) * 2;
    const size_t kvbase = (size_t)(b * S_) * D_ + h * DH_;

    // ---- Q fragments (single fp16, pre-scaled by log2e/8) ----
    uint32_t qh[4][4];
    {
        const size_t qrow = (size_t)(b * S_ + q0 + w * 16 + group);
        const __half* qhp = Q1 + qrow * D_ + h * DH_;
#pragma unroll
        for (int ks = 0; ks < 4; ++ks) {
            const int c = ks * 16 + 2 * tig;
            qh[ks][0] = *(const uint32_t*)(qhp + c);
            qh[ks][1] = *(const uint32_t*)(qhp + 8 * D_ + c);
            qh[ks][2] = *(const uint32_t*)(qhp + c + 8);
            qh[ks][3] = *(const uint32_t*)(qhp + 8 * D_ + c + 8);
        }
    }

    float oacc[8][4];
#pragma unroll
    for (int i = 0; i < 8; ++i)
#pragma unroll
        for (int j = 0; j < 4; ++j) oacc[i][j] = 0.f;
    float lrow[4] = {0.f, 0.f, 0.f, 0.f};   // ones-MMA accumulator (row sums of P)

    auto issue_tile = [&](int t) {
        const size_t g = kvbase + (size_t)(t * 64 + stok) * D_;
        const uint32_t bufb = sb + (uint32_t)(t % 3) * BUF_SZ;
#pragma unroll
        for (int i = 0; i < 2; ++i) {
            const int c = sc0 + i;
            const uint32_t off = (uint32_t)(stok * 128 + ((c ^ (stok & 7)) << 4));
            const size_t ge = g + c * 8;
            CP16(bufb + BK + off, K1 + ge);
            CP16(bufb + BV + off, V1 + ge);
        }
        CP_COMMIT();
    };

    issue_tile(0);
    issue_tile(1);

    for (int t = 0; t < NTILES; ++t) {
        CP_WAIT(1);
        __syncthreads();
        if (t + 2 < NTILES) issue_tile(t + 2);
        else { CP_COMMIT(); }   // keep pending-group count consistent

        const uint32_t bufb = sb + (uint32_t)(t % 3) * BUF_SZ;

#pragma unroll
        for (int ks2 = 0; ks2 < 4; ++ks2) {
            float sacc[2][4];
#pragma unroll
            for (int j = 0; j < 4; ++j) { sacc[0][j] = 0.f; sacc[1][j] = 0.f; }
            const uint32_t ntbase = (uint32_t)(ks2 * 2048);
#pragma unroll
            for (int ks = 0; ks < 4; ++ks) {
                const uint32_t csw = (uint32_t)(((2 * ks + kodd) ^ r_) << 4);
                uint32_t bhv[4];
                ldmx4(bhv, bufb + BK + krow + ntbase + csw);
                mma_f16(sacc[0], qh[ks], bhv[0], bhv[1]);
                mma_f16(sacc[1], qh[ks], bhv[2], bhv[3]);
            }
            const float p00 = ex2f(sacc[0][0]), p01 = ex2f(sacc[0][1]);
            const float p02 = ex2f(sacc[0][2]), p03 = ex2f(sacc[0][3]);
            const float p10 = ex2f(sacc[1][0]), p11 = ex2f(sacc[1][1]);
            const float p12 = ex2f(sacc[1][2]), p13 = ex2f(sacc[1][3]);
            uint32_t pha[4];
            pha[0] = pack2h(p00, p01);
            pha[1] = pack2h(p02, p03);
            pha[2] = pack2h(p10, p11);
            pha[3] = pack2h(p12, p13);

            // row sums of P via ones-matrix MMA (replaces scalar lsum adds)
            mma_f16(lrow, pha, ONES_H2, ONES_H2);

            const uint32_t vrow = (uint32_t)((ks2 * 16 + kodd * 8 + r_) * 128);
#pragma unroll
            for (int ntp = 0; ntp < 4; ++ntp) {
                const uint32_t csw = (uint32_t)(((2 * ntp + rsel) ^ r_) << 4);
                uint32_t bhv[4];
                ldmx4t(bhv, bufb + BV + vrow + csw);
                mma_f16(oacc[2*ntp],     pha, bhv[0], bhv[1]);
                mma_f16(oacc[2*ntp + 1], pha, bhv[2], bhv[3]);
            }
        }
    }

    // lrow[0] = full row sum for row (group), lrow[2] for row (group+8); all lanes agree
    const float inv0 = 1.f / lrow[0];
    const float inv1 = 1.f / lrow[2];

    const size_t orow = (size_t)(b * S_ + q0 + w * 16 + group);
#pragma unroll
    for (int nt = 0; nt < 8; ++nt) {
        const int col = h * DH_ + nt * 8 + 2 * tig;
        *(__half2*)(O1 + orow * D_ + col) =
            __floats2half2_rn(oacc[nt][0] * inv0, oacc[nt][1] * inv0);
        *(__half2*)(O1 + (orow + 8) * D_ + col) =
            __floats2half2_rn(oacc[nt][2] * inv1, oacc[nt][3] * inv1);
    }
}

// ---------------- launch ----------------
extern "C" void kernel_launch(void* const* d_in, const int* in_sizes, int n_in,
                              void* d_out, int out_size)
{
    const float* xq = (const float*)d_in[0];
    const float* xk = (const float*)d_in[1];
    const float* xv = (const float*)d_in[2];
    const float* Wq = (const float*)d_in[3];
    const float* Wk = (const float*)d_in[4];
    const float* Wv = (const float*)d_in[5];
    const float* Wo = (const float*)d_in[6];
    float* out = (float*)d_out;

    void *x0, *x1, *x2, *q1, *k1, *v1, *o1;
    void *w0, *w1, *w2, *w3;
    cudaGetSymbolAddress(&x0, g_x0);
    cudaGetSymbolAddress(&x1, g_x1);
    cudaGetSymbolAddress(&x2, g_x2);
    cudaGetSymbolAddress(&q1, g_q1);
    cudaGetSymbolAddress(&k1, g_k1);
    cudaGetSymbolAddress(&v1, g_v1);
    cudaGetSymbolAddress(&o1, g_o1);
    cudaGetSymbolAddress(&w0, g_w0);
    cudaGetSymbolAddress(&w1, g_w1);
    cudaGetSymbolAddress(&w2, g_w2);
    cudaGetSymbolAddress(&w3, g_w3);

    static int init_done = 0;
    if (!init_done) {
        cudaFuncSetAttribute(attn_mma_kernel, cudaFuncAttributeMaxDynamicSharedMemorySize, ATT_SMEM);
        cudaFuncSetAttribute(gemm_qkv_kernel, cudaFuncAttributeMaxDynamicSharedMemorySize, GSMEM);
        cudaFuncSetAttribute(gemm_out_kernel, cudaFuncAttributeMaxDynamicSharedMemorySize, GSMEM);
        init_done = 1;
    }

    typedef __half hf;

    // prep: single launch (activations + weights)
    dim3 pgrid((M_ * D_ / 4) / 256, 7);
    prep_kernel<<<pgrid, 256>>>(xq, xk, xv, Wq, Wk, Wv, Wo,
                                (hf*)x0, (hf*)x1, (hf*)x2,
                                (hf*)w0, (hf*)w1, (hf*)w2, (hf*)w3);

    // merged Q/K/V projections (single-term A)
    dim3 qkvgrid(D_ / 128, M_ / 128, 3);   // (4, 64, 3)
    gemm_qkv_kernel<<<qkvgrid, 256, GSMEM>>>(
        (hf*)x0, (hf*)x1, (hf*)x2,
        (hf*)w0, (hf*)w1, (hf*)w2,
        (hf*)q1, (hf*)k1, (hf*)v1);

    // attention (kv tile 64, 3 buffers, ones-MMA lsum)
    dim3 agrid(S_ / 128, B_ * H_);   // (16, 32)
    attn_mma_kernel<<<agrid, 256, ATT_SMEM>>>((hf*)q1, (hf*)k1, (hf*)v1, (hf*)o1);

    // output projection (single-term A, fp32 out)
    dim3 ogrid(D_ / 128, M_ / 128);   // (4, 64)
    gemm_out_kernel<<<ogrid, 256, GSMEM>>>((hf*)o1, (hf*)w3, out);
}